// round 1
// baseline (speedup 1.0000x reference)
#include <cuda_runtime.h>

// Problem constants
#define BB 2
#define TT 2048
#define CC 1024
#define HH 16
#define DD 64

// Attention tiling
#define TQ  16     // query rows per block
#define TKT 128    // key tile
#define SP  2056   // scores smem pitch (floats), 2056 % 32 == 8 (conflict-free row pairs)
#define QP  68     // q tile pitch
#define KP  132    // transposed-K tile pitch (over keys)
#define VP  68     // V tile pitch (over cols)

static __device__ float g_qkv[(size_t)BB * TT * 3 * CC];  // [B*T, 3C]
static __device__ float g_att[(size_t)BB * TT * CC];      // [B*T, C] (attn output, pre-proj)

// ---------------------------------------------------------------------------
// Generic tiled fp32 GEMM with bias: C[M,N] = A[M,K] @ B[K,N] + bias[N]
// 64x64 block tile, BK=16, 256 threads, 4x4 register tile per thread.
// ---------------------------------------------------------------------------
__global__ __launch_bounds__(256) void gemm_bias_kernel(
    const float* __restrict__ A, const float* __restrict__ B,
    const float* __restrict__ bias, float* __restrict__ C,
    int M, int N, int K)
{
    __shared__ float As[16][68];  // [k][m]
    __shared__ float Bs[16][68];  // [k][n]
    int tid = threadIdx.x;
    int tx = tid & 15, ty = tid >> 4;
    int m0 = blockIdx.y * 64, n0 = blockIdx.x * 64;

    float acc[4][4] = {};

    for (int k0 = 0; k0 < K; k0 += 16) {
        #pragma unroll
        for (int i = tid; i < 64 * 16; i += 256) {
            int row = i >> 4, kk = i & 15;
            As[kk][row] = A[(size_t)(m0 + row) * K + k0 + kk];
        }
        #pragma unroll
        for (int i = tid; i < 16 * 64; i += 256) {
            int kk = i >> 6, col = i & 63;
            Bs[kk][col] = B[(size_t)(k0 + kk) * N + n0 + col];
        }
        __syncthreads();

        #pragma unroll
        for (int kk = 0; kk < 16; kk++) {
            float4 av = *(const float4*)&As[kk][ty * 4];
            float4 bv = *(const float4*)&Bs[kk][tx * 4];
            float a[4] = {av.x, av.y, av.z, av.w};
            float b[4] = {bv.x, bv.y, bv.z, bv.w};
            #pragma unroll
            for (int i = 0; i < 4; i++)
                #pragma unroll
                for (int j = 0; j < 4; j++)
                    acc[i][j] = fmaf(a[i], b[j], acc[i][j]);
        }
        __syncthreads();
    }

    float4 bia = *(const float4*)&bias[n0 + tx * 4];
    #pragma unroll
    for (int i = 0; i < 4; i++) {
        int m = m0 + ty * 4 + i;
        float4 o;
        o.x = acc[i][0] + bia.x;
        o.y = acc[i][1] + bia.y;
        o.z = acc[i][2] + bia.z;
        o.w = acc[i][3] + bia.w;
        *(float4*)&C[(size_t)m * N + n0 + tx * 4] = o;
    }
}

// ---------------------------------------------------------------------------
// Causal attention. One block per (b, h, 16-query tile). 256 threads.
// Dynamic smem: scores[TQ][SP] | q[TQ][QP] | kv tile (union of K^T and V).
// Writes attn_w (with zeros above diagonal) and attn output into g_att.
// ---------------------------------------------------------------------------
__global__ __launch_bounds__(256) void attn_kernel(
    const float* __restrict__ qkv, float* __restrict__ attw,
    float* __restrict__ attv)
{
    extern __shared__ float sm[];
    float* sc = sm;                    // TQ * SP
    float* qs = sm + TQ * SP;          // TQ * QP
    float* kv = qs + TQ * QP;          // max(64*KP, TKT*VP)

    const int q0 = blockIdx.x * TQ;
    const int h  = blockIdx.y;
    const int b  = blockIdx.z;
    const int tid = threadIdx.x;

    const float scale = 0.125f;  // 1/sqrt(64)
    const size_t rowstride = 3 * CC;
    const float* base = qkv + ((size_t)b * TT) * rowstride;

    // ---- Load Q tile (pre-scaled) ----
    {
        int row = tid >> 4, d4 = (tid & 15) * 4;
        float4 qv = *(const float4*)(base + (size_t)(q0 + row) * rowstride + h * DD + d4);
        float4 qq = make_float4(qv.x * scale, qv.y * scale, qv.z * scale, qv.w * scale);
        *(float4*)&qs[row * QP + d4] = qq;
    }
    __syncthreads();

    const int kend   = q0 + TQ;
    const int ntiles = (kend + TKT - 1) / TKT;
    const int kspan  = ntiles * TKT;

    // ---- Phase 1: scores S = Q K^T (masked) ----
    const int kb = (tid & 31) * 4;      // 4 keys per thread
    const int rb = (tid >> 5) * 2;      // 2 rows per thread

    for (int t = 0; t < ntiles; t++) {
        // load K tile transposed: kv[d][key]
        for (int i = tid; i < TKT * 16; i += 256) {
            int key = i >> 4, d4 = (i & 15) * 4;
            float4 kk4 = *(const float4*)(base + (size_t)(t * TKT + key) * rowstride + CC + h * DD + d4);
            kv[(d4 + 0) * KP + key] = kk4.x;
            kv[(d4 + 1) * KP + key] = kk4.y;
            kv[(d4 + 2) * KP + key] = kk4.z;
            kv[(d4 + 3) * KP + key] = kk4.w;
        }
        __syncthreads();

        float acc[2][4] = {};
        #pragma unroll
        for (int dd = 0; dd < 16; dd++) {
            float kd[4][4];
            #pragma unroll
            for (int dj = 0; dj < 4; dj++) {
                float4 kk4 = *(const float4*)&kv[(dd * 4 + dj) * KP + kb];
                kd[dj][0] = kk4.x; kd[dj][1] = kk4.y; kd[dj][2] = kk4.z; kd[dj][3] = kk4.w;
            }
            #pragma unroll
            for (int r = 0; r < 2; r++) {
                float4 qv = *(const float4*)&qs[(rb + r) * QP + dd * 4];
                float qd[4] = {qv.x, qv.y, qv.z, qv.w};
                #pragma unroll
                for (int dj = 0; dj < 4; dj++)
                    #pragma unroll
                    for (int j = 0; j < 4; j++)
                        acc[r][j] = fmaf(qd[dj], kd[dj][j], acc[r][j]);
            }
        }

        // masked store to scores smem
        int jb = t * TKT + kb;
        #pragma unroll
        for (int r = 0; r < 2; r++) {
            int qg = q0 + rb + r;
            float4 sv;
            sv.x = (jb + 0 <= qg) ? acc[r][0] : -1e30f;
            sv.y = (jb + 1 <= qg) ? acc[r][1] : -1e30f;
            sv.z = (jb + 2 <= qg) ? acc[r][2] : -1e30f;
            sv.w = (jb + 3 <= qg) ? acc[r][3] : -1e30f;
            *(float4*)&sc[(rb + r) * SP + jb] = sv;
        }
        __syncthreads();  // protects kv reuse + sc visibility
    }

    // ---- Phase 2: softmax per row; write attn_w; store p in-place ----
    {
        int warp = tid >> 5, lane = tid & 31;
        for (int r = warp; r < TQ; r += 8) {
            int qg = q0 + r;
            float* row = &sc[r * SP];
            float m = -1e30f;
            for (int j = lane; j < kspan; j += 32) m = fmaxf(m, row[j]);
            #pragma unroll
            for (int o = 16; o; o >>= 1) m = fmaxf(m, __shfl_xor_sync(0xffffffffu, m, o));
            float l = 0.0f;
            for (int j = lane; j < kspan; j += 32) l += __expf(row[j] - m);
            #pragma unroll
            for (int o = 16; o; o >>= 1) l += __shfl_xor_sync(0xffffffffu, l, o);
            float invl = 1.0f / l;

            float* orow = attw ? attw + (((size_t)(b * HH + h) * TT + qg) * TT) : (float*)0;
            for (int j = lane; j < TT; j += 32) {
                float p = 0.0f;
                if (j < kspan) {
                    p = __expf(row[j] - m) * invl;
                    row[j] = p;
                }
                if (orow) orow[j] = p;
            }
        }
    }
    __syncthreads();

    // ---- Phase 3: O = P V ----
    {
        const int pr = tid >> 4;            // row 0..15
        const int cb = (tid & 15) * 4;      // 4 cols
        float oacc[4] = {0.f, 0.f, 0.f, 0.f};

        for (int t = 0; t < ntiles; t++) {
            for (int i = tid; i < TKT * 16; i += 256) {
                int key = i >> 4, c4 = (i & 15) * 4;
                float4 vv = *(const float4*)(base + (size_t)(t * TKT + key) * rowstride + 2 * CC + h * DD + c4);
                *(float4*)&kv[key * VP + c4] = vv;
            }
            __syncthreads();

            const float* prow = &sc[pr * SP + t * TKT];
            #pragma unroll 8
            for (int kk = 0; kk < TKT; kk++) {
                float p = prow[kk];
                float4 vv = *(const float4*)&kv[kk * VP + cb];
                oacc[0] = fmaf(p, vv.x, oacc[0]);
                oacc[1] = fmaf(p, vv.y, oacc[1]);
                oacc[2] = fmaf(p, vv.z, oacc[2]);
                oacc[3] = fmaf(p, vv.w, oacc[3]);
            }
            __syncthreads();
        }
        *(float4*)&attv[((size_t)(b * TT + q0 + pr)) * CC + h * DD + cb] =
            make_float4(oacc[0], oacc[1], oacc[2], oacc[3]);
    }
}

// ---------------------------------------------------------------------------
extern "C" void kernel_launch(void* const* d_in, const int* in_sizes, int n_in,
                              void* d_out, int out_size)
{
    (void)in_sizes; (void)n_in;
    const float* x     = (const float*)d_in[0];
    const float* w_qkv = (const float*)d_in[1];
    const float* b_qkv = (const float*)d_in[2];
    const float* w_o   = (const float*)d_in[3];
    const float* b_o   = (const float*)d_in[4];
    float* out = (float*)d_out;

    float* qkv = 0; float* att = 0;
    cudaGetSymbolAddress((void**)&qkv, g_qkv);
    cudaGetSymbolAddress((void**)&att, g_att);

    // 1) QKV projection: [B*T, C] @ [C, 3C] + b
    dim3 g1(3 * CC / 64, BB * TT / 64);
    gemm_bias_kernel<<<g1, 256>>>(x, w_qkv, b_qkv, qkv, BB * TT, 3 * CC, CC);

    // 2) Attention
    size_t o_elems = (size_t)BB * TT * CC;
    float* attw = ((size_t)out_size > o_elems) ? out + o_elems : (float*)0;

    size_t smem_bytes = (size_t)(TQ * SP + TQ * QP + TKT * VP) * sizeof(float);
    cudaFuncSetAttribute(attn_kernel, cudaFuncAttributeMaxDynamicSharedMemorySize,
                         (int)smem_bytes);
    dim3 g2(TT / TQ, HH, BB);
    attn_kernel<<<g2, 256, smem_bytes>>>(qkv, attw, att);

    // 3) Output projection: [B*T, C] @ [C, C] + b
    dim3 g3(CC / 64, BB * TT / 64);
    gemm_bias_kernel<<<g3, 256>>>(att, w_o, b_o, out, BB * TT, CC, CC);
}

// round 3
// speedup vs baseline: 1.7046x; 1.7046x over previous
#include <cuda_runtime.h>
#include <cuda_bf16.h>
#include <cstdint>

// Problem constants
#define BB 2
#define TT 2048
#define CC 1024
#define HH 16
#define DD 64
#define MM (BB*TT)   // 4096 rows

// Attention tiling
#define TQ  16
#define TKT 256
#define SP  2056
#define QP  68
#define KP2 260
#define VP  68

// ---------------- scratch (no allocs allowed) ----------------
static __device__ __align__(128) float g_qkv[(size_t)MM * 3 * CC];
static __device__ __align__(128) __nv_bfloat16 g_xhi[(size_t)MM * CC], g_xlo[(size_t)MM * CC];
static __device__ __align__(128) __nv_bfloat16 g_w1hi[(size_t)3 * CC * CC], g_w1lo[(size_t)3 * CC * CC];
static __device__ __align__(128) __nv_bfloat16 g_w2hi[(size_t)CC * CC], g_w2lo[(size_t)CC * CC];
static __device__ __align__(128) __nv_bfloat16 g_ahi[(size_t)MM * CC], g_alo[(size_t)MM * CC];

// ---------------- helpers ----------------
__device__ __forceinline__ uint32_t smem_u32(const void* p) {
    uint32_t a;
    asm("{ .reg .u64 t; cvta.to.shared.u64 t, %1; cvt.u32.u64 %0, t; }" : "=r"(a) : "l"(p));
    return a;
}

#define CPASYNC16(dst, src) \
    asm volatile("cp.async.cg.shared.global [%0], [%1], 16;" :: "r"(dst), "l"(src))
#define CP_COMMIT()  asm volatile("cp.async.commit_group;" ::: "memory")
#define CP_WAIT0()   asm volatile("cp.async.wait_group 0;" ::: "memory")

#define LDSM4(r0, r1, r2, r3, addr) \
    asm volatile("ldmatrix.sync.aligned.m8n8.x4.shared.b16 {%0,%1,%2,%3}, [%4];" \
                 : "=r"(r0), "=r"(r1), "=r"(r2), "=r"(r3) : "r"(addr))

#define MMA16816(d, a, b) \
    asm volatile("mma.sync.aligned.m16n8k16.row.col.f32.bf16.bf16.f32 " \
                 "{%0,%1,%2,%3}, {%4,%5,%6,%7}, {%8,%9}, {%0,%1,%2,%3};" \
                 : "+f"((d)[0]), "+f"((d)[1]), "+f"((d)[2]), "+f"((d)[3]) \
                 : "r"((a)[0]), "r"((a)[1]), "r"((a)[2]), "r"((a)[3]), \
                   "r"((b)[0]), "r"((b)[1]))

// ---------------------------------------------------------------------------
// fp32 -> bf16 hi/lo split (elementwise)
// ---------------------------------------------------------------------------
__global__ void split_f32(const float* __restrict__ in, __nv_bfloat16* __restrict__ hi,
                          __nv_bfloat16* __restrict__ lo, int n) {
    int i = blockIdx.x * blockDim.x + threadIdx.x;
    if (i < n) {
        float v = in[i];
        __nv_bfloat16 h = __float2bfloat16(v);
        hi[i] = h;
        lo[i] = __float2bfloat16(v - __bfloat162float(h));
    }
}

// w [K,N] f32 -> wT hi/lo [N,K] bf16
__global__ void transpose_split(const float* __restrict__ w, __nv_bfloat16* __restrict__ hi,
                                __nv_bfloat16* __restrict__ lo, int K, int N) {
    __shared__ float t[32][33];
    int n0 = blockIdx.x * 32, k0 = blockIdx.y * 32;
    int tx = threadIdx.x, ty = threadIdx.y;
    #pragma unroll
    for (int j = 0; j < 32; j += 8)
        t[ty + j][tx] = w[(size_t)(k0 + ty + j) * N + n0 + tx];
    __syncthreads();
    #pragma unroll
    for (int j = 0; j < 32; j += 8) {
        float v = t[tx][ty + j];
        size_t o = (size_t)(n0 + ty + j) * K + k0 + tx;
        __nv_bfloat16 h = __float2bfloat16(v);
        hi[o] = h;
        lo[o] = __float2bfloat16(v - __bfloat162float(h));
    }
}

// ---------------------------------------------------------------------------
// mma.sync bf16 GEMM: C[M,N] = A[M,K] @ B^T + bias   (B given as [N,K] K-major)
// A,B as hi/lo bf16 pairs; 3 accumulating passes emulate fp32.
// CTA tile 128x128, BK=64, 256 threads (8 warps as 2x4), 2-stage cp.async.
// smem per stage: Ah|Al|Bh|Bl, each 128x64 bf16 = 16KB (SW128 permuted rows).
// ---------------------------------------------------------------------------
__global__ __launch_bounds__(256) void mma_gemm(
    const __nv_bfloat16* __restrict__ Ahi, const __nv_bfloat16* __restrict__ Alo,
    const __nv_bfloat16* __restrict__ Bhi, const __nv_bfloat16* __restrict__ Blo,
    const float* __restrict__ bias, float* __restrict__ C, int N, int K)
{
    extern __shared__ char smem[];
    const uint32_t sb = smem_u32(smem);
    const int tid = threadIdx.x;
    const int lane = tid & 31, wid = tid >> 5;
    const int warpM = wid >> 2, warpN = wid & 3;
    const int m0 = blockIdx.y * 128, n0 = blockIdx.x * 128;

    const __nv_bfloat16* pAh = Ahi + (size_t)m0 * K;
    const __nv_bfloat16* pAl = Alo + (size_t)m0 * K;
    const __nv_bfloat16* pBh = Bhi + (size_t)n0 * K;
    const __nv_bfloat16* pBl = Blo + (size_t)n0 * K;

    float acc[4][4][4] = {};
    const int nch = K >> 6;

    // ---- stage load macro: 4 arrays x 1024 16B-chunks, 4 per thread each ----
    #define STAGE_LOAD(stg, kc) do {                                              \
        uint32_t s0_ = sb + (uint32_t)(stg) * 65536u;                             \
        _Pragma("unroll")                                                         \
        for (int i_ = 0; i_ < 4; i_++) {                                          \
            int idx_ = tid + i_ * 256;                                            \
            int row_ = idx_ >> 3, c16_ = idx_ & 7;                                \
            uint32_t so_ = (uint32_t)(row_ * 128 + ((c16_ ^ (row_ & 7)) << 4));   \
            size_t go_ = (size_t)row_ * K + (kc) + c16_ * 8;                      \
            CPASYNC16(s0_ + so_,          pAh + go_);                             \
            CPASYNC16(s0_ + 16384 + so_,  pAl + go_);                             \
            CPASYNC16(s0_ + 32768 + so_,  pBh + go_);                             \
            CPASYNC16(s0_ + 49152 + so_,  pBl + go_);                             \
        }                                                                         \
        CP_COMMIT();                                                              \
    } while (0)

    STAGE_LOAD(0, 0);

    for (int c = 0; c < nch; c++) {
        CP_WAIT0();
        __syncthreads();
        if (c + 1 < nch) STAGE_LOAD((c + 1) & 1, (c + 1) * 64);

        const uint32_t aB  = sb + (uint32_t)(c & 1) * 65536u;
        const uint32_t bB  = aB + 32768;

        #pragma unroll
        for (int k16 = 0; k16 < 4; k16++) {
            uint32_t ah[4][4], al[4][4], bh[4][2], bl[4][2];
            // A fragments: 4 m-tiles of 16x16
            #pragma unroll
            for (int mi = 0; mi < 4; mi++) {
                int row = warpM * 64 + mi * 16 + (lane & 15);
                int c16 = k16 * 2 + (lane >> 4);
                uint32_t ad = aB + (uint32_t)(row * 128 + ((c16 ^ (row & 7)) << 4));
                LDSM4(ah[mi][0], ah[mi][1], ah[mi][2], ah[mi][3], ad);
                LDSM4(al[mi][0], al[mi][1], al[mi][2], al[mi][3], ad + 16384);
            }
            // B fragments: 4 n-tiles of 8, two per ldmatrix.x4
            #pragma unroll
            for (int p = 0; p < 2; p++) {
                int g = lane >> 3, r = lane & 7;
                int row = warpN * 32 + p * 16 + (g >> 1) * 8 + r;
                int c16 = k16 * 2 + (g & 1);
                uint32_t bd = bB + (uint32_t)(row * 128 + ((c16 ^ (row & 7)) << 4));
                uint32_t t0, t1, t2, t3;
                LDSM4(t0, t1, t2, t3, bd);
                bh[2*p][0] = t0; bh[2*p][1] = t1; bh[2*p+1][0] = t2; bh[2*p+1][1] = t3;
                LDSM4(t0, t1, t2, t3, bd + 16384);
                bl[2*p][0] = t0; bl[2*p][1] = t1; bl[2*p+1][0] = t2; bl[2*p+1][1] = t3;
            }
            #pragma unroll
            for (int mi = 0; mi < 4; mi++)
                #pragma unroll
                for (int ni = 0; ni < 4; ni++) {
                    MMA16816(acc[mi][ni], ah[mi], bh[ni]);
                    MMA16816(acc[mi][ni], ah[mi], bl[ni]);
                    MMA16816(acc[mi][ni], al[mi], bh[ni]);
                }
        }
        __syncthreads();
    }

    // ---- epilogue: bias + direct stores ----
    #pragma unroll
    for (int mi = 0; mi < 4; mi++) {
        int row = m0 + warpM * 64 + mi * 16 + (lane >> 2);
        #pragma unroll
        for (int ni = 0; ni < 4; ni++) {
            int col = n0 + warpN * 32 + ni * 8 + (lane & 3) * 2;
            float b0 = bias[col], b1 = bias[col + 1];
            float2 v0 = make_float2(acc[mi][ni][0] + b0, acc[mi][ni][1] + b1);
            float2 v1 = make_float2(acc[mi][ni][2] + b0, acc[mi][ni][3] + b1);
            *(float2*)&C[(size_t)row * N + col] = v0;
            *(float2*)&C[(size_t)(row + 8) * N + col] = v1;
        }
    }
    #undef STAGE_LOAD
}

// ---------------------------------------------------------------------------
// Causal attention. One block per (b, h, 16-query tile). 256 threads.
// Phase1: 256-key tiles, 4x4 per-thread. Phase3: split-K 4 groups, 4x4.
// Emits attn_w (f32) and attention output as bf16 hi/lo split.
// ---------------------------------------------------------------------------
__global__ __launch_bounds__(256, 1) void attn_kernel(
    const float* __restrict__ qkv, float* __restrict__ attw,
    __nv_bfloat16* __restrict__ ohi, __nv_bfloat16* __restrict__ olo)
{
    extern __shared__ float sm[];
    float* sc = sm;                    // TQ * SP
    float* qs = sm + TQ * SP;          // TQ * QP
    float* kv = qs + TQ * QP;          // max(64*KP2, TKT*VP) = 17408 floats

    const int q0 = blockIdx.x * TQ;
    const int h  = blockIdx.y;
    const int b  = blockIdx.z;
    const int tid = threadIdx.x;

    const float scale = 0.125f;
    const size_t rowstride = 3 * CC;
    const float* base = qkv + ((size_t)b * TT) * rowstride;

    // ---- Q tile (pre-scaled) ----
    {
        int row = tid >> 4, d4 = (tid & 15) * 4;
        float4 qv = *(const float4*)(base + (size_t)(q0 + row) * rowstride + h * DD + d4);
        *(float4*)&qs[row * QP + d4] =
            make_float4(qv.x * scale, qv.y * scale, qv.z * scale, qv.w * scale);
    }
    __syncthreads();

    const int kend   = q0 + TQ;
    const int ntiles = (kend + TKT - 1) / TKT;
    const int kspan  = ntiles * TKT;

    // ---- Phase 1: S = Q K^T (masked) ----
    const int rb = (tid >> 6) * 4;      // 4 rows
    const int kb = (tid & 63) * 4;      // 4 keys

    for (int t = 0; t < ntiles; t++) {
        for (int i = tid; i < TKT * 16; i += 256) {
            int key = i >> 4, d4 = (i & 15) * 4;
            float4 k4 = *(const float4*)(base + (size_t)(t * TKT + key) * rowstride + CC + h * DD + d4);
            kv[(d4 + 0) * KP2 + key] = k4.x;
            kv[(d4 + 1) * KP2 + key] = k4.y;
            kv[(d4 + 2) * KP2 + key] = k4.z;
            kv[(d4 + 3) * KP2 + key] = k4.w;
        }
        __syncthreads();

        float acc[4][4] = {};
        #pragma unroll 8
        for (int dd = 0; dd < 64; dd++) {
            float4 k4 = *(const float4*)&kv[dd * KP2 + kb];
            float qv0 = qs[(rb + 0) * QP + dd];
            float qv1 = qs[(rb + 1) * QP + dd];
            float qv2 = qs[(rb + 2) * QP + dd];
            float qv3 = qs[(rb + 3) * QP + dd];
            acc[0][0] = fmaf(qv0, k4.x, acc[0][0]); acc[0][1] = fmaf(qv0, k4.y, acc[0][1]);
            acc[0][2] = fmaf(qv0, k4.z, acc[0][2]); acc[0][3] = fmaf(qv0, k4.w, acc[0][3]);
            acc[1][0] = fmaf(qv1, k4.x, acc[1][0]); acc[1][1] = fmaf(qv1, k4.y, acc[1][1]);
            acc[1][2] = fmaf(qv1, k4.z, acc[1][2]); acc[1][3] = fmaf(qv1, k4.w, acc[1][3]);
            acc[2][0] = fmaf(qv2, k4.x, acc[2][0]); acc[2][1] = fmaf(qv2, k4.y, acc[2][1]);
            acc[2][2] = fmaf(qv2, k4.z, acc[2][2]); acc[2][3] = fmaf(qv2, k4.w, acc[2][3]);
            acc[3][0] = fmaf(qv3, k4.x, acc[3][0]); acc[3][1] = fmaf(qv3, k4.y, acc[3][1]);
            acc[3][2] = fmaf(qv3, k4.z, acc[3][2]); acc[3][3] = fmaf(qv3, k4.w, acc[3][3]);
        }

        int jb = t * TKT + kb;
        #pragma unroll
        for (int r = 0; r < 4; r++) {
            int qg = q0 + rb + r;
            float4 sv;
            sv.x = (jb + 0 <= qg) ? acc[r][0] : -1e30f;
            sv.y = (jb + 1 <= qg) ? acc[r][1] : -1e30f;
            sv.z = (jb + 2 <= qg) ? acc[r][2] : -1e30f;
            sv.w = (jb + 3 <= qg) ? acc[r][3] : -1e30f;
            *(float4*)&sc[(rb + r) * SP + jb] = sv;
        }
        __syncthreads();
    }

    // ---- Phase 2: softmax; write attn_w; keep p in smem ----
    {
        int warp = tid >> 5, lane = tid & 31;
        for (int r = warp; r < TQ; r += 8) {
            int qg = q0 + r;
            float* row = &sc[r * SP];
            float m = -1e30f;
            for (int j = lane; j < kspan; j += 32) m = fmaxf(m, row[j]);
            #pragma unroll
            for (int o = 16; o; o >>= 1) m = fmaxf(m, __shfl_xor_sync(0xffffffffu, m, o));
            float l = 0.0f;
            for (int j = lane; j < kspan; j += 32) l += __expf(row[j] - m);
            #pragma unroll
            for (int o = 16; o; o >>= 1) l += __shfl_xor_sync(0xffffffffu, l, o);
            float invl = 1.0f / l;

            float* orow = attw ? attw + (((size_t)(b * HH + h) * TT + qg) * TT) : (float*)0;
            for (int j = lane; j < TT; j += 32) {
                float p = 0.0f;
                if (j < kspan) {
                    p = __expf(row[j] - m) * invl;
                    row[j] = p;
                }
                if (orow) orow[j] = p;
            }
        }
    }
    __syncthreads();

    // ---- Phase 3: O = P V, split-K over 4 groups ----
    {
        const int g   = tid >> 6;
        const int tg  = tid & 63;
        const int rb3 = (tg >> 4) * 4;
        const int cb3 = (tg & 15) * 4;
        float oa[4][4] = {};

        for (int t = 0; t < ntiles; t++) {
            for (int i = tid; i < TKT * 16; i += 256) {
                int key = i >> 4, c4 = (i & 15) * 4;
                float4 vv = *(const float4*)(base + (size_t)(t * TKT + key) * rowstride + 2 * CC + h * DD + c4);
                *(float4*)&kv[key * VP + c4] = vv;
            }
            __syncthreads();

            const int kbase = t * TKT + g * 64;
            #pragma unroll 4
            for (int kk = 0; kk < 64; kk++) {
                float p0 = sc[(rb3 + 0) * SP + kbase + kk];
                float p1 = sc[(rb3 + 1) * SP + kbase + kk];
                float p2 = sc[(rb3 + 2) * SP + kbase + kk];
                float p3 = sc[(rb3 + 3) * SP + kbase + kk];
                float4 vv = *(const float4*)&kv[(g * 64 + kk) * VP + cb3];
                oa[0][0] = fmaf(p0, vv.x, oa[0][0]); oa[0][1] = fmaf(p0, vv.y, oa[0][1]);
                oa[0][2] = fmaf(p0, vv.z, oa[0][2]); oa[0][3] = fmaf(p0, vv.w, oa[0][3]);
                oa[1][0] = fmaf(p1, vv.x, oa[1][0]); oa[1][1] = fmaf(p1, vv.y, oa[1][1]);
                oa[1][2] = fmaf(p1, vv.z, oa[1][2]); oa[1][3] = fmaf(p1, vv.w, oa[1][3]);
                oa[2][0] = fmaf(p2, vv.x, oa[2][0]); oa[2][1] = fmaf(p2, vv.y, oa[2][1]);
                oa[2][2] = fmaf(p2, vv.z, oa[2][2]); oa[2][3] = fmaf(p2, vv.w, oa[2][3]);
                oa[3][0] = fmaf(p3, vv.x, oa[3][0]); oa[3][1] = fmaf(p3, vv.y, oa[3][1]);
                oa[3][2] = fmaf(p3, vv.z, oa[3][2]); oa[3][3] = fmaf(p3, vv.w, oa[3][3]);
            }
            __syncthreads();
        }

        // partial reduction across the 4 groups (reuse kv)
        #pragma unroll
        for (int r = 0; r < 4; r++)
            *(float4*)&kv[g * 1024 + (rb3 + r) * 64 + cb3] =
                make_float4(oa[r][0], oa[r][1], oa[r][2], oa[r][3]);
        __syncthreads();

        const int pr2 = tid >> 4, cb2 = (tid & 15) * 4;
        float s0 = 0.f, s1 = 0.f, s2 = 0.f, s3 = 0.f;
        #pragma unroll
        for (int gg = 0; gg < 4; gg++) {
            const float* pb = &kv[gg * 1024 + pr2 * 64 + cb2];
            s0 += pb[0]; s1 += pb[1]; s2 += pb[2]; s3 += pb[3];
        }
        size_t obase = ((size_t)(b * TT + q0 + pr2)) * CC + h * DD + cb2;
        float vs[4] = {s0, s1, s2, s3};
        #pragma unroll
        for (int j = 0; j < 4; j++) {
            __nv_bfloat16 hv = __float2bfloat16(vs[j]);
            ohi[obase + j] = hv;
            olo[obase + j] = __float2bfloat16(vs[j] - __bfloat162float(hv));
        }
    }
}

// ---------------------------------------------------------------------------
extern "C" void kernel_launch(void* const* d_in, const int* in_sizes, int n_in,
                              void* d_out, int out_size)
{
    (void)in_sizes; (void)n_in;
    const float* x     = (const float*)d_in[0];
    const float* w_qkv = (const float*)d_in[1];
    const float* b_qkv = (const float*)d_in[2];
    const float* w_o   = (const float*)d_in[3];
    const float* b_o   = (const float*)d_in[4];
    float* out = (float*)d_out;

    float* qkv; __nv_bfloat16 *xhi, *xlo, *w1hi, *w1lo, *w2hi, *w2lo, *ahi, *alo;
    cudaGetSymbolAddress((void**)&qkv, g_qkv);
    cudaGetSymbolAddress((void**)&xhi, g_xhi);   cudaGetSymbolAddress((void**)&xlo, g_xlo);
    cudaGetSymbolAddress((void**)&w1hi, g_w1hi); cudaGetSymbolAddress((void**)&w1lo, g_w1lo);
    cudaGetSymbolAddress((void**)&w2hi, g_w2hi); cudaGetSymbolAddress((void**)&w2lo, g_w2lo);
    cudaGetSymbolAddress((void**)&ahi, g_ahi);   cudaGetSymbolAddress((void**)&alo, g_alo);

    const int gemm_smem = 2 * 65536;
    cudaFuncSetAttribute(mma_gemm, cudaFuncAttributeMaxDynamicSharedMemorySize, gemm_smem);
    const size_t attn_smem = (size_t)(TQ * SP + TQ * QP + 17408) * sizeof(float);
    cudaFuncSetAttribute(attn_kernel, cudaFuncAttributeMaxDynamicSharedMemorySize, (int)attn_smem);

    // prep: split x, transpose+split weights
    split_f32<<<(MM * CC + 1023) / 1024, 1024>>>(x, xhi, xlo, MM * CC);
    transpose_split<<<dim3(3 * CC / 32, CC / 32), dim3(32, 8)>>>(w_qkv, w1hi, w1lo, CC, 3 * CC);
    transpose_split<<<dim3(CC / 32, CC / 32), dim3(32, 8)>>>(w_o, w2hi, w2lo, CC, CC);

    // 1) QKV projection (tensor cores)
    mma_gemm<<<dim3(3 * CC / 128, MM / 128), 256, gemm_smem>>>(
        xhi, xlo, w1hi, w1lo, b_qkv, qkv, 3 * CC, CC);

    // 2) attention
    size_t o_elems = (size_t)MM * CC;
    float* attw = ((size_t)out_size > o_elems) ? out + o_elems : (float*)0;
    dim3 g2(TT / TQ, HH, BB);
    attn_kernel<<<g2, 256, attn_smem>>>(qkv, attw, ahi, alo);

    // 3) output projection (tensor cores)
    mma_gemm<<<dim3(CC / 128, MM / 128), 256, gemm_smem>>>(
        ahi, alo, w2hi, w2lo, b_o, out, CC, CC);
}

// round 4
// speedup vs baseline: 3.0296x; 1.7773x over previous
#include <cuda_runtime.h>
#include <cuda_bf16.h>
#include <cstdint>

// Problem constants
#define BB 2
#define TT 2048
#define CC 1024
#define HH 16
#define DD 64
#define MM (BB*TT)   // 4096 rows

// Attention smem layout (bytes)
#define OFF_SC 0                  // S fp32: 16 rows x 8192 B (P_hi overwrites in place)
#define OFF_PL 131072             // P_lo bf16: 16 rows x 4096 B
#define OFF_KV 196608             // 2 x 16384 B K/V tile buffers (hi 8K + lo 8K each)
#define ATTN_SMEM 229376

// ---------------- scratch (no allocs allowed) ----------------
static __device__ __align__(128) __nv_bfloat16 g_xhi[(size_t)MM * CC], g_xlo[(size_t)MM * CC];
static __device__ __align__(128) __nv_bfloat16 g_w1hi[(size_t)3 * CC * CC], g_w1lo[(size_t)3 * CC * CC];
static __device__ __align__(128) __nv_bfloat16 g_w2hi[(size_t)CC * CC], g_w2lo[(size_t)CC * CC];
static __device__ __align__(128) __nv_bfloat16 g_qh[(size_t)MM * 3 * CC], g_ql[(size_t)MM * 3 * CC];
static __device__ __align__(128) __nv_bfloat16 g_ahi[(size_t)MM * CC], g_alo[(size_t)MM * CC];

// ---------------- helpers ----------------
__device__ __forceinline__ uint32_t smem_u32(const void* p) {
    uint32_t a;
    asm("{ .reg .u64 t; cvta.to.shared.u64 t, %1; cvt.u32.u64 %0, t; }" : "=r"(a) : "l"(p));
    return a;
}

#define CPASYNC16(dst, src) \
    asm volatile("cp.async.cg.shared.global [%0], [%1], 16;" :: "r"(dst), "l"(src))
#define CP_COMMIT()  asm volatile("cp.async.commit_group;" ::: "memory")
#define CP_WAIT0()   asm volatile("cp.async.wait_group 0;" ::: "memory")
#define CP_WAIT1()   asm volatile("cp.async.wait_group 1;" ::: "memory")

#define LDSM4(r0, r1, r2, r3, addr) \
    asm volatile("ldmatrix.sync.aligned.m8n8.x4.shared.b16 {%0,%1,%2,%3}, [%4];" \
                 : "=r"(r0), "=r"(r1), "=r"(r2), "=r"(r3) : "r"(addr))

#define LDSM4T(r0, r1, r2, r3, addr) \
    asm volatile("ldmatrix.sync.aligned.m8n8.x4.trans.shared.b16 {%0,%1,%2,%3}, [%4];" \
                 : "=r"(r0), "=r"(r1), "=r"(r2), "=r"(r3) : "r"(addr))

#define MMA16816(d, a, b) \
    asm volatile("mma.sync.aligned.m16n8k16.row.col.f32.bf16.bf16.f32 " \
                 "{%0,%1,%2,%3}, {%4,%5,%6,%7}, {%8,%9}, {%0,%1,%2,%3};" \
                 : "+f"((d)[0]), "+f"((d)[1]), "+f"((d)[2]), "+f"((d)[3]) \
                 : "r"((a)[0]), "r"((a)[1]), "r"((a)[2]), "r"((a)[3]), \
                   "r"((b)[0]), "r"((b)[1]))

// ---------------------------------------------------------------------------
// fp32 -> bf16 hi/lo split (elementwise)
// ---------------------------------------------------------------------------
__global__ void split_f32(const float* __restrict__ in, __nv_bfloat16* __restrict__ hi,
                          __nv_bfloat16* __restrict__ lo, int n) {
    int i = blockIdx.x * blockDim.x + threadIdx.x;
    if (i < n) {
        float v = in[i];
        __nv_bfloat16 h = __float2bfloat16(v);
        hi[i] = h;
        lo[i] = __float2bfloat16(v - __bfloat162float(h));
    }
}

// w [K,N] f32 -> wT hi/lo [N,K] bf16
__global__ void transpose_split(const float* __restrict__ w, __nv_bfloat16* __restrict__ hi,
                                __nv_bfloat16* __restrict__ lo, int K, int N) {
    __shared__ float t[32][33];
    int n0 = blockIdx.x * 32, k0 = blockIdx.y * 32;
    int tx = threadIdx.x, ty = threadIdx.y;
    #pragma unroll
    for (int j = 0; j < 32; j += 8)
        t[ty + j][tx] = w[(size_t)(k0 + ty + j) * N + n0 + tx];
    __syncthreads();
    #pragma unroll
    for (int j = 0; j < 32; j += 8) {
        float v = t[tx][ty + j];
        size_t o = (size_t)(n0 + ty + j) * K + k0 + tx;
        __nv_bfloat16 h = __float2bfloat16(v);
        hi[o] = h;
        lo[o] = __float2bfloat16(v - __bfloat162float(h));
    }
}

// ---------------------------------------------------------------------------
// mma.sync bf16 GEMM: C = A @ B^T + bias (B as [N,K]); optional bf16-split out.
// ---------------------------------------------------------------------------
__global__ __launch_bounds__(256) void mma_gemm(
    const __nv_bfloat16* __restrict__ Ahi, const __nv_bfloat16* __restrict__ Alo,
    const __nv_bfloat16* __restrict__ Bhi, const __nv_bfloat16* __restrict__ Blo,
    const float* __restrict__ bias, float* __restrict__ C,
    __nv_bfloat16* __restrict__ Chi, __nv_bfloat16* __restrict__ Clo,
    int N, int K)
{
    extern __shared__ char smem[];
    const uint32_t sb = smem_u32(smem);
    const int tid = threadIdx.x;
    const int lane = tid & 31, wid = tid >> 5;
    const int warpM = wid >> 2, warpN = wid & 3;
    const int m0 = blockIdx.y * 128, n0 = blockIdx.x * 128;

    const __nv_bfloat16* pAh = Ahi + (size_t)m0 * K;
    const __nv_bfloat16* pAl = Alo + (size_t)m0 * K;
    const __nv_bfloat16* pBh = Bhi + (size_t)n0 * K;
    const __nv_bfloat16* pBl = Blo + (size_t)n0 * K;

    float acc[4][4][4] = {};
    const int nch = K >> 6;

    #define STAGE_LOAD(stg, kc) do {                                              \
        uint32_t s0_ = sb + (uint32_t)(stg) * 65536u;                             \
        _Pragma("unroll")                                                         \
        for (int i_ = 0; i_ < 4; i_++) {                                          \
            int idx_ = tid + i_ * 256;                                            \
            int row_ = idx_ >> 3, c16_ = idx_ & 7;                                \
            uint32_t so_ = (uint32_t)(row_ * 128 + ((c16_ ^ (row_ & 7)) << 4));   \
            size_t go_ = (size_t)row_ * K + (kc) + c16_ * 8;                      \
            CPASYNC16(s0_ + so_,          pAh + go_);                             \
            CPASYNC16(s0_ + 16384 + so_,  pAl + go_);                             \
            CPASYNC16(s0_ + 32768 + so_,  pBh + go_);                             \
            CPASYNC16(s0_ + 49152 + so_,  pBl + go_);                             \
        }                                                                         \
        CP_COMMIT();                                                              \
    } while (0)

    STAGE_LOAD(0, 0);

    for (int c = 0; c < nch; c++) {
        CP_WAIT0();
        __syncthreads();
        if (c + 1 < nch) STAGE_LOAD((c + 1) & 1, (c + 1) * 64);

        const uint32_t aB  = sb + (uint32_t)(c & 1) * 65536u;
        const uint32_t bB  = aB + 32768;

        #pragma unroll
        for (int k16 = 0; k16 < 4; k16++) {
            uint32_t ah[4][4], al[4][4], bh[4][2], bl[4][2];
            #pragma unroll
            for (int mi = 0; mi < 4; mi++) {
                int row = warpM * 64 + mi * 16 + (lane & 15);
                int c16 = k16 * 2 + (lane >> 4);
                uint32_t ad = aB + (uint32_t)(row * 128 + ((c16 ^ (row & 7)) << 4));
                LDSM4(ah[mi][0], ah[mi][1], ah[mi][2], ah[mi][3], ad);
                LDSM4(al[mi][0], al[mi][1], al[mi][2], al[mi][3], ad + 16384);
            }
            #pragma unroll
            for (int p = 0; p < 2; p++) {
                int g = lane >> 3, r = lane & 7;
                int row = warpN * 32 + p * 16 + (g >> 1) * 8 + r;
                int c16 = k16 * 2 + (g & 1);
                uint32_t bd = bB + (uint32_t)(row * 128 + ((c16 ^ (row & 7)) << 4));
                uint32_t t0, t1, t2, t3;
                LDSM4(t0, t1, t2, t3, bd);
                bh[2*p][0] = t0; bh[2*p][1] = t1; bh[2*p+1][0] = t2; bh[2*p+1][1] = t3;
                LDSM4(t0, t1, t2, t3, bd + 16384);
                bl[2*p][0] = t0; bl[2*p][1] = t1; bl[2*p+1][0] = t2; bl[2*p+1][1] = t3;
            }
            #pragma unroll
            for (int mi = 0; mi < 4; mi++)
                #pragma unroll
                for (int ni = 0; ni < 4; ni++) {
                    MMA16816(acc[mi][ni], ah[mi], bh[ni]);
                    MMA16816(acc[mi][ni], ah[mi], bl[ni]);
                    MMA16816(acc[mi][ni], al[mi], bh[ni]);
                }
        }
        __syncthreads();
    }

    #pragma unroll
    for (int mi = 0; mi < 4; mi++) {
        int row = m0 + warpM * 64 + mi * 16 + (lane >> 2);
        #pragma unroll
        for (int ni = 0; ni < 4; ni++) {
            int col = n0 + warpN * 32 + ni * 8 + (lane & 3) * 2;
            float b0 = bias[col], b1 = bias[col + 1];
            float v00 = acc[mi][ni][0] + b0, v01 = acc[mi][ni][1] + b1;
            float v10 = acc[mi][ni][2] + b0, v11 = acc[mi][ni][3] + b1;
            if (Chi) {
                __nv_bfloat162 hh, ll;
                hh.x = __float2bfloat16(v00); hh.y = __float2bfloat16(v01);
                ll.x = __float2bfloat16(v00 - __bfloat162float(hh.x));
                ll.y = __float2bfloat16(v01 - __bfloat162float(hh.y));
                *(__nv_bfloat162*)&Chi[(size_t)row * N + col] = hh;
                *(__nv_bfloat162*)&Clo[(size_t)row * N + col] = ll;
                hh.x = __float2bfloat16(v10); hh.y = __float2bfloat16(v11);
                ll.x = __float2bfloat16(v10 - __bfloat162float(hh.x));
                ll.y = __float2bfloat16(v11 - __bfloat162float(hh.y));
                *(__nv_bfloat162*)&Chi[(size_t)(row + 8) * N + col] = hh;
                *(__nv_bfloat162*)&Clo[(size_t)(row + 8) * N + col] = ll;
            } else {
                *(float2*)&C[(size_t)row * N + col] = make_float2(v00, v01);
                *(float2*)&C[(size_t)(row + 8) * N + col] = make_float2(v10, v11);
            }
        }
    }
    #undef STAGE_LOAD
}

// ---------------------------------------------------------------------------
// Tensor-core causal attention. Block = (b, h, 16-query tile), 256 threads.
// ---------------------------------------------------------------------------
__global__ __launch_bounds__(256, 1) void attn_fa(
    const __nv_bfloat16* __restrict__ qkh, const __nv_bfloat16* __restrict__ qkl,
    float* __restrict__ attw,
    __nv_bfloat16* __restrict__ oh, __nv_bfloat16* __restrict__ ol)
{
    extern __shared__ char smem[];
    const uint32_t sb = smem_u32(smem);
    const int tid = threadIdx.x, lane = tid & 31, wid = tid >> 5;
    const int q0 = blockIdx.x * 16;
    const int h  = blockIdx.y;
    const int b  = blockIdx.z;
    const int bT = b * TT;

    const int kend   = q0 + 16;
    const int ntiles = (kend + 63) >> 6;
    const int kspan  = ntiles * 64;
    const float scale = 0.125f;

    // issue one K/V tile (64 rows x 64 cols, hi+lo) into stage buffer
    #define ISSUE_KV(tile, stg, colbase) do {                                       \
        _Pragma("unroll")                                                           \
        for (int i_ = 0; i_ < 4; i_++) {                                            \
            int idx_ = tid + i_ * 256;                                              \
            int wh_ = idx_ >> 9, rr_ = (idx_ >> 3) & 63, cc_ = idx_ & 7;            \
            const __nv_bfloat16* src_ = (wh_ ? qkl : qkh) +                         \
                (size_t)(bT + (tile) * 64 + rr_) * 3072 + (colbase) + cc_ * 8;      \
            uint32_t dst_ = sb + OFF_KV + (uint32_t)(stg) * 16384u +                \
                (uint32_t)(wh_ * 8192 + rr_ * 128 + ((cc_ ^ (rr_ & 7)) << 4));      \
            CPASYNC16(dst_, src_);                                                  \
        }                                                                           \
        CP_COMMIT();                                                                \
    } while (0)

    // ---- Stage Q through buffer 0, load fragments to registers ----
    uint32_t qfh[4][4], qfl[4][4];
    {
        int wh_ = tid >> 7, rr_ = (tid >> 3) & 15, cc_ = tid & 7;
        const __nv_bfloat16* src_ = (wh_ ? qkl : qkh) +
            (size_t)(bT + q0 + rr_) * 3072 + h * 64 + cc_ * 8;
        uint32_t dst_ = sb + OFF_KV + (uint32_t)(wh_ * 2048 + rr_ * 128 + ((cc_ ^ (rr_ & 7)) << 4));
        CPASYNC16(dst_, src_);
        CP_COMMIT(); CP_WAIT0();
        __syncthreads();
        #pragma unroll
        for (int k16 = 0; k16 < 4; k16++) {
            int r = lane & 15;
            int c16 = k16 * 2 + (lane >> 4);
            uint32_t ad = sb + OFF_KV + (uint32_t)(r * 128 + ((c16 ^ (r & 7)) << 4));
            LDSM4(qfh[k16][0], qfh[k16][1], qfh[k16][2], qfh[k16][3], ad);
            LDSM4(qfl[k16][0], qfl[k16][1], qfl[k16][2], qfl[k16][3], ad + 2048);
        }
        __syncthreads();
    }

    // ---- Phase 1: S = Q K^T, fp32 to smem ----
    const int n0w = wid * 8;
    ISSUE_KV(0, 0, CC + h * 64);
    for (int t = 0; t < ntiles; t++) {
        if (t + 1 < ntiles) { ISSUE_KV(t + 1, (t + 1) & 1, CC + h * 64); CP_WAIT1(); }
        else CP_WAIT0();
        __syncthreads();

        const uint32_t kb = sb + OFF_KV + (uint32_t)(t & 1) * 16384u;
        float sa[4] = {0.f, 0.f, 0.f, 0.f};
        #pragma unroll
        for (int k32 = 0; k32 < 2; k32++) {
            int rk = n0w + (lane & 7);
            int c16 = k32 * 4 + (lane >> 3);
            uint32_t ad = kb + (uint32_t)(rk * 128 + ((c16 ^ (rk & 7)) << 4));
            uint32_t kh[4], kl[4];
            LDSM4(kh[0], kh[1], kh[2], kh[3], ad);
            LDSM4(kl[0], kl[1], kl[2], kl[3], ad + 8192);
            uint32_t bh0[2] = {kh[0], kh[1]}, bh1[2] = {kh[2], kh[3]};
            uint32_t bl0[2] = {kl[0], kl[1]}, bl1[2] = {kl[2], kl[3]};
            MMA16816(sa, qfh[k32*2],     bh0);
            MMA16816(sa, qfh[k32*2],     bl0);
            MMA16816(sa, qfl[k32*2],     bh0);
            MMA16816(sa, qfh[k32*2 + 1], bh1);
            MMA16816(sa, qfh[k32*2 + 1], bl1);
            MMA16816(sa, qfl[k32*2 + 1], bh1);
        }
        int j0 = t * 64 + n0w + (lane & 3) * 2;
        int r0 = lane >> 2;
        int qg = q0 + r0;
        float2 v;
        v.x = (j0     <= qg) ? sa[0] * scale : -1e30f;
        v.y = (j0 + 1 <= qg) ? sa[1] * scale : -1e30f;
        *(float2*)(smem + OFF_SC + r0 * 8192 + j0 * 4) = v;
        int qg2 = qg + 8;
        float2 w;
        w.x = (j0     <= qg2) ? sa[2] * scale : -1e30f;
        w.y = (j0 + 1 <= qg2) ? sa[3] * scale : -1e30f;
        *(float2*)(smem + OFF_SC + (r0 + 8) * 8192 + j0 * 4) = w;
        __syncthreads();
    }

    // ---- Phase 2: softmax; write attn_w; P -> bf16 hi/lo swizzled ----
    for (int rr = wid; rr < 16; rr += 8) {
        int qg = q0 + rr;
        float* row = (float*)(smem + OFF_SC + rr * 8192);
        float mx = -1e30f;
        for (int j = lane; j < kspan; j += 32) mx = fmaxf(mx, row[j]);
        #pragma unroll
        for (int o = 16; o; o >>= 1) mx = fmaxf(mx, __shfl_xor_sync(0xffffffffu, mx, o));
        float l = 0.0f;
        for (int j = lane; j < kspan; j += 32) {
            float p = __expf(row[j] - mx);
            row[j] = p;
            l += p;
        }
        #pragma unroll
        for (int o = 16; o; o >>= 1) l += __shfl_xor_sync(0xffffffffu, l, o);
        float invl = 1.0f / l;

        float* orow = attw ? attw + (((size_t)(b * HH + h) * TT + qg) * TT) : (float*)0;
        char* hrow = smem + OFF_SC + rr * 8192;
        char* lrow = smem + OFF_PL + rr * 4096;
        for (int j = lane; j < kspan; j += 32) {
            float p = row[j] * invl;          // read (4j) happens before writes (2j-ish)
            if (orow) orow[j] = p;
            unsigned tj = 2u * (unsigned)j;
            unsigned sw = (tj & ~127u) | (((((tj >> 4) & 7u) ^ ((unsigned)rr & 7u)) << 4)) | (tj & 15u);
            __nv_bfloat16 hp = __float2bfloat16(p);
            *(__nv_bfloat16*)(hrow + sw) = hp;
            *(__nv_bfloat16*)(lrow + sw) = __float2bfloat16(p - __bfloat162float(hp));
        }
        if (orow)
            for (int j = kspan + lane; j < TT; j += 32) orow[j] = 0.0f;
    }
    __syncthreads();

    // ---- Phase 3: O = P V ----
    float oa[4] = {0.f, 0.f, 0.f, 0.f};
    ISSUE_KV(0, 0, 2 * CC + h * 64);
    for (int t = 0; t < ntiles; t++) {
        if (t + 1 < ntiles) { ISSUE_KV(t + 1, (t + 1) & 1, 2 * CC + h * 64); CP_WAIT1(); }
        else CP_WAIT0();
        __syncthreads();

        const uint32_t vb = sb + OFF_KV + (uint32_t)(t & 1) * 16384u;
        #pragma unroll
        for (int k32 = 0; k32 < 2; k32++) {
            int rv = k32 * 32 + (lane >> 3) * 8 + (lane & 7);
            uint32_t ad = vb + (uint32_t)(rv * 128 + ((wid ^ (rv & 7)) << 4));
            uint32_t vh[4], vl[4];
            LDSM4T(vh[0], vh[1], vh[2], vh[3], ad);
            LDSM4T(vl[0], vl[1], vl[2], vl[3], ad + 8192);
            #pragma unroll
            for (int s = 0; s < 2; s++) {
                int Cc = t * 8 + k32 * 4 + s * 2 + (lane >> 4);
                int r = lane & 15;
                uint32_t sw = (uint32_t)(((Cc & ~7) | ((Cc & 7) ^ (r & 7))) << 4);
                uint32_t ph[4], pl[4];
                LDSM4(ph[0], ph[1], ph[2], ph[3], sb + OFF_SC + (uint32_t)(r * 8192) + sw);
                LDSM4(pl[0], pl[1], pl[2], pl[3], sb + OFF_PL + (uint32_t)(r * 4096) + sw);
                uint32_t bvh[2] = {vh[s*2], vh[s*2+1]};
                uint32_t bvl[2] = {vl[s*2], vl[s*2+1]};
                MMA16816(oa, ph, bvh);
                MMA16816(oa, ph, bvl);
                MMA16816(oa, pl, bvh);
            }
        }
        __syncthreads();
    }

    // ---- epilogue: O as bf16 hi/lo ----
    {
        int m = lane >> 2;
        int col = h * 64 + wid * 8 + (lane & 3) * 2;
        size_t r1 = (size_t)(bT + q0 + m) * CC + col;
        size_t r2 = (size_t)(bT + q0 + m + 8) * CC + col;
        __nv_bfloat162 hh, ll;
        hh.x = __float2bfloat16(oa[0]); hh.y = __float2bfloat16(oa[1]);
        ll.x = __float2bfloat16(oa[0] - __bfloat162float(hh.x));
        ll.y = __float2bfloat16(oa[1] - __bfloat162float(hh.y));
        *(__nv_bfloat162*)&oh[r1] = hh; *(__nv_bfloat162*)&ol[r1] = ll;
        hh.x = __float2bfloat16(oa[2]); hh.y = __float2bfloat16(oa[3]);
        ll.x = __float2bfloat16(oa[2] - __bfloat162float(hh.x));
        ll.y = __float2bfloat16(oa[3] - __bfloat162float(hh.y));
        *(__nv_bfloat162*)&oh[r2] = hh; *(__nv_bfloat162*)&ol[r2] = ll;
    }
    #undef ISSUE_KV
}

// ---------------------------------------------------------------------------
extern "C" void kernel_launch(void* const* d_in, const int* in_sizes, int n_in,
                              void* d_out, int out_size)
{
    (void)in_sizes; (void)n_in;
    const float* x     = (const float*)d_in[0];
    const float* w_qkv = (const float*)d_in[1];
    const float* b_qkv = (const float*)d_in[2];
    const float* w_o   = (const float*)d_in[3];
    const float* b_o   = (const float*)d_in[4];
    float* out = (float*)d_out;

    __nv_bfloat16 *xhi, *xlo, *w1hi, *w1lo, *w2hi, *w2lo, *qh, *ql, *ahi, *alo;
    cudaGetSymbolAddress((void**)&xhi, g_xhi);   cudaGetSymbolAddress((void**)&xlo, g_xlo);
    cudaGetSymbolAddress((void**)&w1hi, g_w1hi); cudaGetSymbolAddress((void**)&w1lo, g_w1lo);
    cudaGetSymbolAddress((void**)&w2hi, g_w2hi); cudaGetSymbolAddress((void**)&w2lo, g_w2lo);
    cudaGetSymbolAddress((void**)&qh, g_qh);     cudaGetSymbolAddress((void**)&ql, g_ql);
    cudaGetSymbolAddress((void**)&ahi, g_ahi);   cudaGetSymbolAddress((void**)&alo, g_alo);

    const int gemm_smem = 2 * 65536;
    cudaFuncSetAttribute(mma_gemm, cudaFuncAttributeMaxDynamicSharedMemorySize, gemm_smem);
    cudaFuncSetAttribute(attn_fa, cudaFuncAttributeMaxDynamicSharedMemorySize, ATTN_SMEM);

    // prep
    split_f32<<<(MM * CC + 1023) / 1024, 1024>>>(x, xhi, xlo, MM * CC);
    transpose_split<<<dim3(3 * CC / 32, CC / 32), dim3(32, 8)>>>(w_qkv, w1hi, w1lo, CC, 3 * CC);
    transpose_split<<<dim3(CC / 32, CC / 32), dim3(32, 8)>>>(w_o, w2hi, w2lo, CC, CC);

    // 1) QKV projection -> bf16 hi/lo
    mma_gemm<<<dim3(3 * CC / 128, MM / 128), 256, gemm_smem>>>(
        xhi, xlo, w1hi, w1lo, b_qkv, (float*)0, qh, ql, 3 * CC, CC);

    // 2) attention (tensor cores)
    size_t o_elems = (size_t)MM * CC;
    float* attw = ((size_t)out_size > o_elems) ? out + o_elems : (float*)0;
    dim3 g2(TT / 16, HH, BB);
    attn_fa<<<g2, 256, ATTN_SMEM>>>(qh, ql, attw, ahi, alo);

    // 3) output projection
    mma_gemm<<<dim3(CC / 128, MM / 128), 256, gemm_smem>>>(
        ahi, alo, w2hi, w2lo, b_o, out, (__nv_bfloat16*)0, (__nv_bfloat16*)0, CC, CC);
}

// round 5
// speedup vs baseline: 4.1495x; 1.3697x over previous
#include <cuda_runtime.h>
#include <cuda_bf16.h>
#include <cstdint>

// Problem constants
#define BB 2
#define TT 2048
#define CC 1024
#define HH 16
#define DD 64
#define MM (BB*TT)   // 4096 rows

// Attention smem (bytes): K stages 2x16KB @0, V stages 2x16KB @32768,
// stats @65536 (smax 2x64 f32, ssum 2x64 f32). O-reduce reuses @0 (16KB).
#define OFF_VB   32768
#define OFF_SMAX 65536
#define OFF_SSUM 66048
#define ATTN_SMEM 66560

// ---------------- scratch (no allocs allowed) ----------------
static __device__ __align__(128) __nv_bfloat16 g_xhi[(size_t)MM * CC], g_xlo[(size_t)MM * CC];
static __device__ __align__(128) __nv_bfloat16 g_w1hi[(size_t)3 * CC * CC], g_w1lo[(size_t)3 * CC * CC];
static __device__ __align__(128) __nv_bfloat16 g_w2hi[(size_t)CC * CC], g_w2lo[(size_t)CC * CC];
static __device__ __align__(128) __nv_bfloat16 g_qh[(size_t)MM * 3 * CC], g_ql[(size_t)MM * 3 * CC];
static __device__ __align__(128) __nv_bfloat16 g_ahi[(size_t)MM * CC], g_alo[(size_t)MM * CC];

// ---------------- helpers ----------------
__device__ __forceinline__ uint32_t smem_u32(const void* p) {
    uint32_t a;
    asm("{ .reg .u64 t; cvta.to.shared.u64 t, %1; cvt.u32.u64 %0, t; }" : "=r"(a) : "l"(p));
    return a;
}

#define CPASYNC16(dst, src) \
    asm volatile("cp.async.cg.shared.global [%0], [%1], 16;" :: "r"(dst), "l"(src))
#define CP_COMMIT()  asm volatile("cp.async.commit_group;" ::: "memory")
#define CP_WAIT0()   asm volatile("cp.async.wait_group 0;" ::: "memory")
#define CP_WAIT1()   asm volatile("cp.async.wait_group 1;" ::: "memory")

#define LDSM4(r0, r1, r2, r3, addr) \
    asm volatile("ldmatrix.sync.aligned.m8n8.x4.shared.b16 {%0,%1,%2,%3}, [%4];" \
                 : "=r"(r0), "=r"(r1), "=r"(r2), "=r"(r3) : "r"(addr))

#define LDSM4T(r0, r1, r2, r3, addr) \
    asm volatile("ldmatrix.sync.aligned.m8n8.x4.trans.shared.b16 {%0,%1,%2,%3}, [%4];" \
                 : "=r"(r0), "=r"(r1), "=r"(r2), "=r"(r3) : "r"(addr))

#define MMA16816(d, a, b) \
    asm volatile("mma.sync.aligned.m16n8k16.row.col.f32.bf16.bf16.f32 " \
                 "{%0,%1,%2,%3}, {%4,%5,%6,%7}, {%8,%9}, {%0,%1,%2,%3};" \
                 : "+f"((d)[0]), "+f"((d)[1]), "+f"((d)[2]), "+f"((d)[3]) \
                 : "r"((a)[0]), "r"((a)[1]), "r"((a)[2]), "r"((a)[3]), \
                   "r"((b)[0]), "r"((b)[1]))

__device__ __forceinline__ uint32_t pack2bf(float a, float b) {
    __nv_bfloat162 t;
    t.x = __float2bfloat16(a); t.y = __float2bfloat16(b);
    return *(uint32_t*)&t;
}
__device__ __forceinline__ float bf_res(float v) {
    return v - __bfloat162float(__float2bfloat16(v));
}

// ---------------------------------------------------------------------------
// prep kernels
// ---------------------------------------------------------------------------
__global__ void split_f32(const float* __restrict__ in, __nv_bfloat16* __restrict__ hi,
                          __nv_bfloat16* __restrict__ lo, int n) {
    int i = blockIdx.x * blockDim.x + threadIdx.x;
    if (i < n) {
        float v = in[i];
        __nv_bfloat16 h = __float2bfloat16(v);
        hi[i] = h;
        lo[i] = __float2bfloat16(v - __bfloat162float(h));
    }
}

__global__ void transpose_split(const float* __restrict__ w, __nv_bfloat16* __restrict__ hi,
                                __nv_bfloat16* __restrict__ lo, int K, int N) {
    __shared__ float t[32][33];
    int n0 = blockIdx.x * 32, k0 = blockIdx.y * 32;
    int tx = threadIdx.x, ty = threadIdx.y;
    #pragma unroll
    for (int j = 0; j < 32; j += 8)
        t[ty + j][tx] = w[(size_t)(k0 + ty + j) * N + n0 + tx];
    __syncthreads();
    #pragma unroll
    for (int j = 0; j < 32; j += 8) {
        float v = t[tx][ty + j];
        size_t o = (size_t)(n0 + ty + j) * K + k0 + tx;
        __nv_bfloat16 h = __float2bfloat16(v);
        hi[o] = h;
        lo[o] = __float2bfloat16(v - __bfloat162float(h));
    }
}

// ---------------------------------------------------------------------------
// mma.sync bf16 GEMM (unchanged from round 4)
// ---------------------------------------------------------------------------
__global__ __launch_bounds__(256) void mma_gemm(
    const __nv_bfloat16* __restrict__ Ahi, const __nv_bfloat16* __restrict__ Alo,
    const __nv_bfloat16* __restrict__ Bhi, const __nv_bfloat16* __restrict__ Blo,
    const float* __restrict__ bias, float* __restrict__ C,
    __nv_bfloat16* __restrict__ Chi, __nv_bfloat16* __restrict__ Clo,
    int N, int K)
{
    extern __shared__ char smem[];
    const uint32_t sb = smem_u32(smem);
    const int tid = threadIdx.x;
    const int lane = tid & 31, wid = tid >> 5;
    const int warpM = wid >> 2, warpN = wid & 3;
    const int m0 = blockIdx.y * 128, n0 = blockIdx.x * 128;

    const __nv_bfloat16* pAh = Ahi + (size_t)m0 * K;
    const __nv_bfloat16* pAl = Alo + (size_t)m0 * K;
    const __nv_bfloat16* pBh = Bhi + (size_t)n0 * K;
    const __nv_bfloat16* pBl = Blo + (size_t)n0 * K;

    float acc[4][4][4] = {};
    const int nch = K >> 6;

    #define STAGE_LOAD(stg, kc) do {                                              \
        uint32_t s0_ = sb + (uint32_t)(stg) * 65536u;                             \
        _Pragma("unroll")                                                         \
        for (int i_ = 0; i_ < 4; i_++) {                                          \
            int idx_ = tid + i_ * 256;                                            \
            int row_ = idx_ >> 3, c16_ = idx_ & 7;                                \
            uint32_t so_ = (uint32_t)(row_ * 128 + ((c16_ ^ (row_ & 7)) << 4));   \
            size_t go_ = (size_t)row_ * K + (kc) + c16_ * 8;                      \
            CPASYNC16(s0_ + so_,          pAh + go_);                             \
            CPASYNC16(s0_ + 16384 + so_,  pAl + go_);                             \
            CPASYNC16(s0_ + 32768 + so_,  pBh + go_);                             \
            CPASYNC16(s0_ + 49152 + so_,  pBl + go_);                             \
        }                                                                         \
        CP_COMMIT();                                                              \
    } while (0)

    STAGE_LOAD(0, 0);

    for (int c = 0; c < nch; c++) {
        CP_WAIT0();
        __syncthreads();
        if (c + 1 < nch) STAGE_LOAD((c + 1) & 1, (c + 1) * 64);

        const uint32_t aB  = sb + (uint32_t)(c & 1) * 65536u;
        const uint32_t bB  = aB + 32768;

        #pragma unroll
        for (int k16 = 0; k16 < 4; k16++) {
            uint32_t ah[4][4], al[4][4], bh[4][2], bl[4][2];
            #pragma unroll
            for (int mi = 0; mi < 4; mi++) {
                int row = warpM * 64 + mi * 16 + (lane & 15);
                int c16 = k16 * 2 + (lane >> 4);
                uint32_t ad = aB + (uint32_t)(row * 128 + ((c16 ^ (row & 7)) << 4));
                LDSM4(ah[mi][0], ah[mi][1], ah[mi][2], ah[mi][3], ad);
                LDSM4(al[mi][0], al[mi][1], al[mi][2], al[mi][3], ad + 16384);
            }
            #pragma unroll
            for (int p = 0; p < 2; p++) {
                int g = lane >> 3, r = lane & 7;
                int row = warpN * 32 + p * 16 + (g >> 1) * 8 + r;
                int c16 = k16 * 2 + (g & 1);
                uint32_t bd = bB + (uint32_t)(row * 128 + ((c16 ^ (row & 7)) << 4));
                uint32_t t0, t1, t2, t3;
                LDSM4(t0, t1, t2, t3, bd);
                bh[2*p][0] = t0; bh[2*p][1] = t1; bh[2*p+1][0] = t2; bh[2*p+1][1] = t3;
                LDSM4(t0, t1, t2, t3, bd + 16384);
                bl[2*p][0] = t0; bl[2*p][1] = t1; bl[2*p+1][0] = t2; bl[2*p+1][1] = t3;
            }
            #pragma unroll
            for (int mi = 0; mi < 4; mi++)
                #pragma unroll
                for (int ni = 0; ni < 4; ni++) {
                    MMA16816(acc[mi][ni], ah[mi], bh[ni]);
                    MMA16816(acc[mi][ni], ah[mi], bl[ni]);
                    MMA16816(acc[mi][ni], al[mi], bh[ni]);
                }
        }
        __syncthreads();
    }

    #pragma unroll
    for (int mi = 0; mi < 4; mi++) {
        int row = m0 + warpM * 64 + mi * 16 + (lane >> 2);
        #pragma unroll
        for (int ni = 0; ni < 4; ni++) {
            int col = n0 + warpN * 32 + ni * 8 + (lane & 3) * 2;
            float b0 = bias[col], b1 = bias[col + 1];
            float v00 = acc[mi][ni][0] + b0, v01 = acc[mi][ni][1] + b1;
            float v10 = acc[mi][ni][2] + b0, v11 = acc[mi][ni][3] + b1;
            if (Chi) {
                __nv_bfloat162 hh, ll;
                hh.x = __float2bfloat16(v00); hh.y = __float2bfloat16(v01);
                ll.x = __float2bfloat16(v00 - __bfloat162float(hh.x));
                ll.y = __float2bfloat16(v01 - __bfloat162float(hh.y));
                *(__nv_bfloat162*)&Chi[(size_t)row * N + col] = hh;
                *(__nv_bfloat162*)&Clo[(size_t)row * N + col] = ll;
                hh.x = __float2bfloat16(v10); hh.y = __float2bfloat16(v11);
                ll.x = __float2bfloat16(v10 - __bfloat162float(hh.x));
                ll.y = __float2bfloat16(v11 - __bfloat162float(hh.y));
                *(__nv_bfloat162*)&Chi[(size_t)(row + 8) * N + col] = hh;
                *(__nv_bfloat162*)&Clo[(size_t)(row + 8) * N + col] = ll;
            } else {
                *(float2*)&C[(size_t)row * N + col] = make_float2(v00, v01);
                *(float2*)&C[(size_t)(row + 8) * N + col] = make_float2(v10, v11);
            }
        }
    }
    #undef STAGE_LOAD
}

// ---------------------------------------------------------------------------
// Two-pass flash attention, TQ=64, 256 threads (8 warps: 4 row-groups x 2
// key/col-groups). No S storage; pass B recomputes S deterministically.
// ---------------------------------------------------------------------------
__global__ __launch_bounds__(256, 2) void attn_fa(
    const __nv_bfloat16* __restrict__ qkh, const __nv_bfloat16* __restrict__ qkl,
    float* __restrict__ attw,
    __nv_bfloat16* __restrict__ oh, __nv_bfloat16* __restrict__ ol)
{
    extern __shared__ char smem[];
    const uint32_t sb = smem_u32(smem);
    float* smax = (float*)(smem + OFF_SMAX);
    float* ssum = (float*)(smem + OFF_SSUM);
    const int tid = threadIdx.x, lane = tid & 31, wid = tid >> 5;
    const int rg = wid >> 1, cg = wid & 1;
    const int q0 = (int)(gridDim.x - 1 - blockIdx.x) * 64;   // big blocks first
    const int h  = blockIdx.y;
    const int b  = blockIdx.z;
    const int bT = b * TT;
    const int ntiles = (q0 >> 6) + 1;
    const int kspan  = ntiles * 64;
    const float scale = 0.125f;

    const int lr0 = rg * 16 + (lane >> 2);     // local row 0..63
    const int lr1 = lr0 + 8;
    const int qg0 = q0 + lr0, qg1 = q0 + lr1;  // global rows

    // stage a 64x64 tile (hi+lo) of qkv columns [colbase, colbase+64)
    #define ISSUE_T(tile, bufoff, colbase) do {                                     \
        _Pragma("unroll")                                                           \
        for (int i_ = 0; i_ < 4; i_++) {                                            \
            int idx_ = tid + i_ * 256;                                              \
            int wh_ = idx_ >> 9, rr_ = (idx_ >> 3) & 63, cc_ = idx_ & 7;            \
            const __nv_bfloat16* src_ = (wh_ ? qkl : qkh) +                         \
                (size_t)(bT + (tile) * 64 + rr_) * 3072 + (colbase) + cc_ * 8;      \
            uint32_t dst_ = sb + (uint32_t)(bufoff) +                               \
                (uint32_t)(wh_ * 8192 + rr_ * 128 + ((cc_ ^ (rr_ & 7)) << 4));      \
            CPASYNC16(dst_, src_);                                                  \
        }                                                                           \
    } while (0)

    // compute S fragments from K buffer into sa[4][4]
    #define COMPUTE_S(sa, kbuf) do {                                                \
        _Pragma("unroll")                                                           \
        for (int k32_ = 0; k32_ < 2; k32_++) {                                      \
            _Pragma("unroll")                                                       \
            for (int nt_ = 0; nt_ < 4; nt_++) {                                     \
                int rk_ = cg * 32 + nt_ * 8 + (lane & 7);                           \
                int c16_ = k32_ * 4 + (lane >> 3);                                  \
                uint32_t ad_ = (kbuf) + (uint32_t)(rk_ * 128 + ((c16_ ^ (rk_ & 7)) << 4)); \
                uint32_t kh_[4], kl_[4];                                            \
                LDSM4(kh_[0], kh_[1], kh_[2], kh_[3], ad_);                         \
                LDSM4(kl_[0], kl_[1], kl_[2], kl_[3], ad_ + 8192);                  \
                uint32_t bh0_[2] = {kh_[0], kh_[1]}, bh1_[2] = {kh_[2], kh_[3]};    \
                uint32_t bl0_[2] = {kl_[0], kl_[1]}, bl1_[2] = {kl_[2], kl_[3]};    \
                MMA16816(sa[nt_], qfh[k32_*2],     bh0_);                           \
                MMA16816(sa[nt_], qfh[k32_*2],     bl0_);                           \
                MMA16816(sa[nt_], qfl[k32_*2],     bh0_);                           \
                MMA16816(sa[nt_], qfh[k32_*2 + 1], bh1_);                           \
                MMA16816(sa[nt_], qfh[k32_*2 + 1], bl1_);                           \
                MMA16816(sa[nt_], qfl[k32_*2 + 1], bh1_);                           \
            }                                                                       \
        }                                                                           \
    } while (0)

    // ---- Stage Q tile through buffer 0; load fragments ----
    uint32_t qfh[4][4], qfl[4][4];
    ISSUE_T(q0 >> 6, 0, h * 64);
    CP_COMMIT(); CP_WAIT0();
    __syncthreads();
    #pragma unroll
    for (int c = 0; c < 4; c++) {
        int row = rg * 16 + (lane & 15);
        int c16 = c * 2 + (lane >> 4);
        uint32_t ad = sb + (uint32_t)(row * 128 + ((c16 ^ (row & 7)) << 4));
        LDSM4(qfh[c][0], qfh[c][1], qfh[c][2], qfh[c][3], ad);
        LDSM4(qfl[c][0], qfl[c][1], qfl[c][2], qfl[c][3], ad + 8192);
    }
    __syncthreads();

    // ---- zero tail of attn_w (cols >= kspan) ----
    if (attw && kspan < TT) {
        float4 z = make_float4(0.f, 0.f, 0.f, 0.f);
        const int ntail4 = (TT - kspan) >> 2;
        float* wb = attw + ((size_t)(b * HH + h) * TT + q0) * TT;
        for (int i = tid; i < 64 * ntail4; i += 256) {
            int r = i / ntail4, c = i - r * ntail4;
            *(float4*)(wb + (size_t)r * TT + kspan + c * 4) = z;
        }
    }

    // ---- Pass A: online softmax stats ----
    float m0 = -1e30f, m1 = -1e30f, l0 = 0.f, l1 = 0.f;

    ISSUE_T(0, 0, CC + h * 64); CP_COMMIT();
    for (int t = 0; t < ntiles; t++) {
        if (t + 1 < ntiles) { ISSUE_T(t + 1, (t + 1) & 1 ? 16384 : 0, CC + h * 64); CP_COMMIT(); CP_WAIT1(); }
        else CP_WAIT0();
        __syncthreads();

        float sa[4][4] = {};
        COMPUTE_S(sa, sb + (uint32_t)((t & 1) ? 16384 : 0));

        float v0[8], v1[8];
        #pragma unroll
        for (int nt = 0; nt < 4; nt++) {
            int j0 = t * 64 + cg * 32 + nt * 8 + (lane & 3) * 2;
            v0[2*nt]   = (j0     <= qg0) ? sa[nt][0] * scale : -1e30f;
            v0[2*nt+1] = (j0 + 1 <= qg0) ? sa[nt][1] * scale : -1e30f;
            v1[2*nt]   = (j0     <= qg1) ? sa[nt][2] * scale : -1e30f;
            v1[2*nt+1] = (j0 + 1 <= qg1) ? sa[nt][3] * scale : -1e30f;
        }
        float mx0 = v0[0], mx1 = v1[0];
        #pragma unroll
        for (int i = 1; i < 8; i++) { mx0 = fmaxf(mx0, v0[i]); mx1 = fmaxf(mx1, v1[i]); }
        mx0 = fmaxf(mx0, __shfl_xor_sync(0xffffffffu, mx0, 1));
        mx0 = fmaxf(mx0, __shfl_xor_sync(0xffffffffu, mx0, 2));
        mx1 = fmaxf(mx1, __shfl_xor_sync(0xffffffffu, mx1, 1));
        mx1 = fmaxf(mx1, __shfl_xor_sync(0xffffffffu, mx1, 2));
        if ((lane & 3) == 0) { smax[cg * 64 + lr0] = mx0; smax[cg * 64 + lr1] = mx1; }
        __syncthreads();
        float mn0 = fmaxf(m0, fmaxf(smax[lr0], smax[64 + lr0]));
        float mn1 = fmaxf(m1, fmaxf(smax[lr1], smax[64 + lr1]));
        float s0 = 0.f, s1 = 0.f;
        #pragma unroll
        for (int i = 0; i < 8; i++) { s0 += __expf(v0[i] - mn0); s1 += __expf(v1[i] - mn1); }
        s0 += __shfl_xor_sync(0xffffffffu, s0, 1);
        s0 += __shfl_xor_sync(0xffffffffu, s0, 2);
        s1 += __shfl_xor_sync(0xffffffffu, s1, 1);
        s1 += __shfl_xor_sync(0xffffffffu, s1, 2);
        if ((lane & 3) == 0) { ssum[cg * 64 + lr0] = s0; ssum[cg * 64 + lr1] = s1; }
        __syncthreads();
        l0 = l0 * __expf(m0 - mn0) + ssum[lr0] + ssum[64 + lr0];
        l1 = l1 * __expf(m1 - mn1) + ssum[lr1] + ssum[64 + lr1];
        m0 = mn0; m1 = mn1;
    }
    const float invl0 = 1.0f / l0, invl1 = 1.0f / l1;

    // ---- Pass B: recompute S, emit attn_w, PV accumulate ----
    float oa[8][4] = {};
    float* wrow0 = attw ? attw + (((size_t)(b * HH + h) * TT + qg0) * TT) : (float*)0;
    float* wrow1 = attw ? attw + (((size_t)(b * HH + h) * TT + qg1) * TT) : (float*)0;

    ISSUE_T(0, 0, CC + h * 64);
    ISSUE_T(0, OFF_VB, 2 * CC + h * 64);
    CP_COMMIT();
    for (int t = 0; t < ntiles; t++) {
        if (t + 1 < ntiles) {
            uint32_t st = ((t + 1) & 1) ? 16384u : 0u;
            ISSUE_T(t + 1, st, CC + h * 64);
            ISSUE_T(t + 1, OFF_VB + st, 2 * CC + h * 64);
            CP_COMMIT(); CP_WAIT1();
        } else CP_WAIT0();
        __syncthreads();

        const uint32_t st = ((t & 1) ? 16384u : 0u);
        float sa[4][4] = {};
        COMPUTE_S(sa, sb + st);

        float p[4][4];
        #pragma unroll
        for (int nt = 0; nt < 4; nt++) {
            int j0 = t * 64 + cg * 32 + nt * 8 + (lane & 3) * 2;
            p[nt][0] = (j0     <= qg0) ? __expf(sa[nt][0] * scale - m0) * invl0 : 0.f;
            p[nt][1] = (j0 + 1 <= qg0) ? __expf(sa[nt][1] * scale - m0) * invl0 : 0.f;
            p[nt][2] = (j0     <= qg1) ? __expf(sa[nt][2] * scale - m1) * invl1 : 0.f;
            p[nt][3] = (j0 + 1 <= qg1) ? __expf(sa[nt][3] * scale - m1) * invl1 : 0.f;
            if (wrow0) {
                *(float2*)(wrow0 + j0) = make_float2(p[nt][0], p[nt][1]);
                *(float2*)(wrow1 + j0) = make_float2(p[nt][2], p[nt][3]);
            }
        }

        // P -> bf16 hi/lo a-fragments (2 k16 blocks over this warp's 32 keys)
        uint32_t pah[2][4], pal[2][4];
        #pragma unroll
        for (int kb = 0; kb < 2; kb++) {
            pah[kb][0] = pack2bf(p[2*kb][0],   p[2*kb][1]);
            pah[kb][1] = pack2bf(p[2*kb][2],   p[2*kb][3]);
            pah[kb][2] = pack2bf(p[2*kb+1][0], p[2*kb+1][1]);
            pah[kb][3] = pack2bf(p[2*kb+1][2], p[2*kb+1][3]);
            pal[kb][0] = pack2bf(bf_res(p[2*kb][0]),   bf_res(p[2*kb][1]));
            pal[kb][1] = pack2bf(bf_res(p[2*kb][2]),   bf_res(p[2*kb][3]));
            pal[kb][2] = pack2bf(bf_res(p[2*kb+1][0]), bf_res(p[2*kb+1][1]));
            pal[kb][3] = pack2bf(bf_res(p[2*kb+1][2]), bf_res(p[2*kb+1][3]));
        }

        // PV: V^T fragments over this warp's 32 keys, all 64 dims
        const uint32_t vbuf = sb + OFF_VB + st;
        #pragma unroll
        for (int nd = 0; nd < 8; nd++) {
            int rv = cg * 32 + (lane >> 3) * 8 + (lane & 7);
            uint32_t ad = vbuf + (uint32_t)(rv * 128 + ((nd ^ (rv & 7)) << 4));
            uint32_t vh[4], vl[4];
            LDSM4T(vh[0], vh[1], vh[2], vh[3], ad);
            LDSM4T(vl[0], vl[1], vl[2], vl[3], ad + 8192);
            #pragma unroll
            for (int kb = 0; kb < 2; kb++) {
                uint32_t bvh[2] = {vh[kb*2], vh[kb*2+1]};
                uint32_t bvl[2] = {vl[kb*2], vl[kb*2+1]};
                MMA16816(oa[nd], pah[kb], bvh);
                MMA16816(oa[nd], pah[kb], bvl);
                MMA16816(oa[nd], pal[kb], bvh);
            }
        }
        __syncthreads();
    }

    // ---- reduce col-group pairs, emit bf16 hi/lo ----
    float* ored = (float*)smem;   // 64 x 64 fp32 (reuses K buffers)
    if (cg == 1) {
        #pragma unroll
        for (int nd = 0; nd < 8; nd++) {
            int d0 = nd * 8 + (lane & 3) * 2;
            *(float2*)&ored[lr0 * 64 + d0] = make_float2(oa[nd][0], oa[nd][1]);
            *(float2*)&ored[lr1 * 64 + d0] = make_float2(oa[nd][2], oa[nd][3]);
        }
    }
    __syncthreads();
    if (cg == 0) {
        #pragma unroll
        for (int nd = 0; nd < 8; nd++) {
            int d0 = nd * 8 + (lane & 3) * 2;
            float2 q0v = *(float2*)&ored[lr0 * 64 + d0];
            float2 q1v = *(float2*)&ored[lr1 * 64 + d0];
            float a0 = oa[nd][0] + q0v.x, a1 = oa[nd][1] + q0v.y;
            float a2 = oa[nd][2] + q1v.x, a3 = oa[nd][3] + q1v.y;
            size_t r1 = (size_t)(bT + qg0) * CC + h * 64 + d0;
            size_t r2 = (size_t)(bT + qg1) * CC + h * 64 + d0;
            __nv_bfloat162 hh, ll;
            hh.x = __float2bfloat16(a0); hh.y = __float2bfloat16(a1);
            ll.x = __float2bfloat16(a0 - __bfloat162float(hh.x));
            ll.y = __float2bfloat16(a1 - __bfloat162float(hh.y));
            *(__nv_bfloat162*)&oh[r1] = hh; *(__nv_bfloat162*)&ol[r1] = ll;
            hh.x = __float2bfloat16(a2); hh.y = __float2bfloat16(a3);
            ll.x = __float2bfloat16(a2 - __bfloat162float(hh.x));
            ll.y = __float2bfloat16(a3 - __bfloat162float(hh.y));
            *(__nv_bfloat162*)&oh[r2] = hh; *(__nv_bfloat162*)&ol[r2] = ll;
        }
    }
    #undef ISSUE_T
    #undef COMPUTE_S
}

// ---------------------------------------------------------------------------
extern "C" void kernel_launch(void* const* d_in, const int* in_sizes, int n_in,
                              void* d_out, int out_size)
{
    (void)in_sizes; (void)n_in;
    const float* x     = (const float*)d_in[0];
    const float* w_qkv = (const float*)d_in[1];
    const float* b_qkv = (const float*)d_in[2];
    const float* w_o   = (const float*)d_in[3];
    const float* b_o   = (const float*)d_in[4];
    float* out = (float*)d_out;

    __nv_bfloat16 *xhi, *xlo, *w1hi, *w1lo, *w2hi, *w2lo, *qh, *ql, *ahi, *alo;
    cudaGetSymbolAddress((void**)&xhi, g_xhi);   cudaGetSymbolAddress((void**)&xlo, g_xlo);
    cudaGetSymbolAddress((void**)&w1hi, g_w1hi); cudaGetSymbolAddress((void**)&w1lo, g_w1lo);
    cudaGetSymbolAddress((void**)&w2hi, g_w2hi); cudaGetSymbolAddress((void**)&w2lo, g_w2lo);
    cudaGetSymbolAddress((void**)&qh, g_qh);     cudaGetSymbolAddress((void**)&ql, g_ql);
    cudaGetSymbolAddress((void**)&ahi, g_ahi);   cudaGetSymbolAddress((void**)&alo, g_alo);

    const int gemm_smem = 2 * 65536;
    cudaFuncSetAttribute(mma_gemm, cudaFuncAttributeMaxDynamicSharedMemorySize, gemm_smem);
    cudaFuncSetAttribute(attn_fa, cudaFuncAttributeMaxDynamicSharedMemorySize, ATTN_SMEM);

    // prep
    split_f32<<<(MM * CC + 1023) / 1024, 1024>>>(x, xhi, xlo, MM * CC);
    transpose_split<<<dim3(3 * CC / 32, CC / 32), dim3(32, 8)>>>(w_qkv, w1hi, w1lo, CC, 3 * CC);
    transpose_split<<<dim3(CC / 32, CC / 32), dim3(32, 8)>>>(w_o, w2hi, w2lo, CC, CC);

    // 1) QKV projection -> bf16 hi/lo
    mma_gemm<<<dim3(3 * CC / 128, MM / 128), 256, gemm_smem>>>(
        xhi, xlo, w1hi, w1lo, b_qkv, (float*)0, qh, ql, 3 * CC, CC);

    // 2) attention (two-pass flash, tensor cores)
    size_t o_elems = (size_t)MM * CC;
    float* attw = ((size_t)out_size > o_elems) ? out + o_elems : (float*)0;
    dim3 g2(TT / 64, HH, BB);
    attn_fa<<<g2, 256, ATTN_SMEM>>>(qh, ql, attw, ahi, alo);

    // 3) output projection
    mma_gemm<<<dim3(CC / 128, MM / 128), 256, gemm_smem>>>(
        ahi, alo, w2hi, w2lo, b_o, out, (__nv_bfloat16*)0, (__nv_bfloat16*)0, CC, CC);
}

// round 6
// speedup vs baseline: 4.2168x; 1.0162x over previous
#include <cuda_runtime.h>
#include <cuda_bf16.h>
#include <cstdint>

// Problem constants
#define BB 2
#define TT 2048
#define CC 1024
#define HH 16
#define DD 64
#define MM (BB*TT)   // 4096 rows

// Attention smem: 3 stages x 32KB (K hi/lo 16KB | V hi/lo 16KB), ssum @98304
#define STG_SZ   32768
#define OFF_SSUM 98304
#define ATTN_SMEM 98816

// ---------------- scratch (no allocs allowed) ----------------
static __device__ __align__(128) __nv_bfloat16 g_xhi[(size_t)MM * CC], g_xlo[(size_t)MM * CC];
static __device__ __align__(128) __nv_bfloat16 g_w1hi[(size_t)3 * CC * CC], g_w1lo[(size_t)3 * CC * CC];
static __device__ __align__(128) __nv_bfloat16 g_w2hi[(size_t)CC * CC], g_w2lo[(size_t)CC * CC];
static __device__ __align__(128) __nv_bfloat16 g_qh[(size_t)MM * 3 * CC], g_ql[(size_t)MM * 3 * CC];
static __device__ __align__(128) __nv_bfloat16 g_ahi[(size_t)MM * CC], g_alo[(size_t)MM * CC];

// ---------------- helpers ----------------
__device__ __forceinline__ uint32_t smem_u32(const void* p) {
    uint32_t a;
    asm("{ .reg .u64 t; cvta.to.shared.u64 t, %1; cvt.u32.u64 %0, t; }" : "=r"(a) : "l"(p));
    return a;
}

#define CPASYNC16(dst, src) \
    asm volatile("cp.async.cg.shared.global [%0], [%1], 16;" :: "r"(dst), "l"(src))
#define CP_COMMIT()  asm volatile("cp.async.commit_group;" ::: "memory")
#define CP_WAIT0()   asm volatile("cp.async.wait_group 0;" ::: "memory")
#define CP_WAIT1()   asm volatile("cp.async.wait_group 1;" ::: "memory")

#define LDSM4(r0, r1, r2, r3, addr) \
    asm volatile("ldmatrix.sync.aligned.m8n8.x4.shared.b16 {%0,%1,%2,%3}, [%4];" \
                 : "=r"(r0), "=r"(r1), "=r"(r2), "=r"(r3) : "r"(addr))

#define LDSM4T(r0, r1, r2, r3, addr) \
    asm volatile("ldmatrix.sync.aligned.m8n8.x4.trans.shared.b16 {%0,%1,%2,%3}, [%4];" \
                 : "=r"(r0), "=r"(r1), "=r"(r2), "=r"(r3) : "r"(addr))

#define MMA16816(d, a, b) \
    asm volatile("mma.sync.aligned.m16n8k16.row.col.f32.bf16.bf16.f32 " \
                 "{%0,%1,%2,%3}, {%4,%5,%6,%7}, {%8,%9}, {%0,%1,%2,%3};" \
                 : "+f"((d)[0]), "+f"((d)[1]), "+f"((d)[2]), "+f"((d)[3]) \
                 : "r"((a)[0]), "r"((a)[1]), "r"((a)[2]), "r"((a)[3]), \
                   "r"((b)[0]), "r"((b)[1]))

__device__ __forceinline__ uint32_t pack2bf(float a, float b) {
    __nv_bfloat162 t;
    t.x = __float2bfloat16(a); t.y = __float2bfloat16(b);
    return *(uint32_t*)&t;
}
__device__ __forceinline__ float bf_res(float v) {
    return v - __bfloat162float(__float2bfloat16(v));
}

// ---------------------------------------------------------------------------
// prep kernels
// ---------------------------------------------------------------------------
__global__ void split_f32(const float* __restrict__ in, __nv_bfloat16* __restrict__ hi,
                          __nv_bfloat16* __restrict__ lo, int n) {
    int i = blockIdx.x * blockDim.x + threadIdx.x;
    if (i < n) {
        float v = in[i];
        __nv_bfloat16 h = __float2bfloat16(v);
        hi[i] = h;
        lo[i] = __float2bfloat16(v - __bfloat162float(h));
    }
}

__global__ void transpose_split(const float* __restrict__ w, __nv_bfloat16* __restrict__ hi,
                                __nv_bfloat16* __restrict__ lo, int K, int N) {
    __shared__ float t[32][33];
    int n0 = blockIdx.x * 32, k0 = blockIdx.y * 32;
    int tx = threadIdx.x, ty = threadIdx.y;
    #pragma unroll
    for (int j = 0; j < 32; j += 8)
        t[ty + j][tx] = w[(size_t)(k0 + ty + j) * N + n0 + tx];
    __syncthreads();
    #pragma unroll
    for (int j = 0; j < 32; j += 8) {
        float v = t[tx][ty + j];
        size_t o = (size_t)(n0 + ty + j) * K + k0 + tx;
        __nv_bfloat16 h = __float2bfloat16(v);
        hi[o] = h;
        lo[o] = __float2bfloat16(v - __bfloat162float(h));
    }
}

// ---------------------------------------------------------------------------
// mma.sync bf16 GEMM, 3-stage cp.async pipeline, one barrier per chunk.
// ---------------------------------------------------------------------------
__global__ __launch_bounds__(256) void mma_gemm(
    const __nv_bfloat16* __restrict__ Ahi, const __nv_bfloat16* __restrict__ Alo,
    const __nv_bfloat16* __restrict__ Bhi, const __nv_bfloat16* __restrict__ Blo,
    const float* __restrict__ bias, float* __restrict__ C,
    __nv_bfloat16* __restrict__ Chi, __nv_bfloat16* __restrict__ Clo,
    int N, int K)
{
    extern __shared__ char smem[];
    const uint32_t sb = smem_u32(smem);
    const int tid = threadIdx.x;
    const int lane = tid & 31, wid = tid >> 5;
    const int warpM = wid >> 2, warpN = wid & 3;
    const int m0 = blockIdx.y * 128, n0 = blockIdx.x * 128;

    const __nv_bfloat16* pAh = Ahi + (size_t)m0 * K;
    const __nv_bfloat16* pAl = Alo + (size_t)m0 * K;
    const __nv_bfloat16* pBh = Bhi + (size_t)n0 * K;
    const __nv_bfloat16* pBl = Blo + (size_t)n0 * K;

    float acc[4][4][4] = {};
    const int nch = K >> 6;

    #define STAGE_LOAD(stg, kc) do {                                              \
        uint32_t s0_ = sb + (uint32_t)(stg) * 65536u;                             \
        _Pragma("unroll")                                                         \
        for (int i_ = 0; i_ < 4; i_++) {                                          \
            int idx_ = tid + i_ * 256;                                            \
            int row_ = idx_ >> 3, c16_ = idx_ & 7;                                \
            uint32_t so_ = (uint32_t)(row_ * 128 + ((c16_ ^ (row_ & 7)) << 4));   \
            size_t go_ = (size_t)row_ * K + (kc) + c16_ * 8;                      \
            CPASYNC16(s0_ + so_,          pAh + go_);                             \
            CPASYNC16(s0_ + 16384 + so_,  pAl + go_);                             \
            CPASYNC16(s0_ + 32768 + so_,  pBh + go_);                             \
            CPASYNC16(s0_ + 49152 + so_,  pBl + go_);                             \
        }                                                                         \
        CP_COMMIT();                                                              \
    } while (0)

    STAGE_LOAD(0, 0);
    if (nch > 1) STAGE_LOAD(1, 64);

    for (int c = 0; c < nch; c++) {
        if (c + 1 < nch) CP_WAIT1();
        else CP_WAIT0();
        __syncthreads();
        if (c + 2 < nch) STAGE_LOAD((c + 2) % 3, (c + 2) * 64);

        const uint32_t aB = sb + (uint32_t)(c % 3) * 65536u;
        const uint32_t bB = aB + 32768;

        #pragma unroll
        for (int k16 = 0; k16 < 4; k16++) {
            uint32_t ah[4][4], al[4][4], bh[4][2], bl[4][2];
            #pragma unroll
            for (int mi = 0; mi < 4; mi++) {
                int row = warpM * 64 + mi * 16 + (lane & 15);
                int c16 = k16 * 2 + (lane >> 4);
                uint32_t ad = aB + (uint32_t)(row * 128 + ((c16 ^ (row & 7)) << 4));
                LDSM4(ah[mi][0], ah[mi][1], ah[mi][2], ah[mi][3], ad);
                LDSM4(al[mi][0], al[mi][1], al[mi][2], al[mi][3], ad + 16384);
            }
            #pragma unroll
            for (int p = 0; p < 2; p++) {
                int g = lane >> 3, r = lane & 7;
                int row = warpN * 32 + p * 16 + (g >> 1) * 8 + r;
                int c16 = k16 * 2 + (g & 1);
                uint32_t bd = bB + (uint32_t)(row * 128 + ((c16 ^ (row & 7)) << 4));
                uint32_t t0, t1, t2, t3;
                LDSM4(t0, t1, t2, t3, bd);
                bh[2*p][0] = t0; bh[2*p][1] = t1; bh[2*p+1][0] = t2; bh[2*p+1][1] = t3;
                LDSM4(t0, t1, t2, t3, bd + 16384);
                bl[2*p][0] = t0; bl[2*p][1] = t1; bl[2*p+1][0] = t2; bl[2*p+1][1] = t3;
            }
            #pragma unroll
            for (int mi = 0; mi < 4; mi++)
                #pragma unroll
                for (int ni = 0; ni < 4; ni++) {
                    MMA16816(acc[mi][ni], ah[mi], bh[ni]);
                    MMA16816(acc[mi][ni], ah[mi], bl[ni]);
                    MMA16816(acc[mi][ni], al[mi], bh[ni]);
                }
        }
    }

    #pragma unroll
    for (int mi = 0; mi < 4; mi++) {
        int row = m0 + warpM * 64 + mi * 16 + (lane >> 2);
        #pragma unroll
        for (int ni = 0; ni < 4; ni++) {
            int col = n0 + warpN * 32 + ni * 8 + (lane & 3) * 2;
            float b0 = bias[col], b1 = bias[col + 1];
            float v00 = acc[mi][ni][0] + b0, v01 = acc[mi][ni][1] + b1;
            float v10 = acc[mi][ni][2] + b0, v11 = acc[mi][ni][3] + b1;
            if (Chi) {
                __nv_bfloat162 hh, ll;
                hh.x = __float2bfloat16(v00); hh.y = __float2bfloat16(v01);
                ll.x = __float2bfloat16(v00 - __bfloat162float(hh.x));
                ll.y = __float2bfloat16(v01 - __bfloat162float(hh.y));
                *(__nv_bfloat162*)&Chi[(size_t)row * N + col] = hh;
                *(__nv_bfloat162*)&Clo[(size_t)row * N + col] = ll;
                hh.x = __float2bfloat16(v10); hh.y = __float2bfloat16(v11);
                ll.x = __float2bfloat16(v10 - __bfloat162float(hh.x));
                ll.y = __float2bfloat16(v11 - __bfloat162float(hh.y));
                *(__nv_bfloat162*)&Chi[(size_t)(row + 8) * N + col] = hh;
                *(__nv_bfloat162*)&Clo[(size_t)(row + 8) * N + col] = ll;
            } else {
                *(float2*)&C[(size_t)row * N + col] = make_float2(v00, v01);
                *(float2*)&C[(size_t)(row + 8) * N + col] = make_float2(v10, v11);
            }
        }
    }
    #undef STAGE_LOAD
}

// ---------------------------------------------------------------------------
// Two-pass flash attention, TQ=64, no running max (scores bounded), 3-stage
// pipeline, one barrier per tile.
// ---------------------------------------------------------------------------
__global__ __launch_bounds__(256, 2) void attn_fa(
    const __nv_bfloat16* __restrict__ qkh, const __nv_bfloat16* __restrict__ qkl,
    float* __restrict__ attw,
    __nv_bfloat16* __restrict__ oh, __nv_bfloat16* __restrict__ ol)
{
    extern __shared__ char smem[];
    const uint32_t sb = smem_u32(smem);
    float* ssum = (float*)(smem + OFF_SSUM);
    const int tid = threadIdx.x, lane = tid & 31, wid = tid >> 5;
    const int rg = wid >> 1, cg = wid & 1;
    const int q0 = (int)(gridDim.x - 1 - blockIdx.x) * 64;   // big blocks first
    const int h  = blockIdx.y;
    const int b  = blockIdx.z;
    const int bT = b * TT;
    const int ntiles = (q0 >> 6) + 1;
    const int kspan  = ntiles * 64;
    const float scale = 0.125f;

    const int lr0 = rg * 16 + (lane >> 2);
    const int lr1 = lr0 + 8;
    const int qg0 = q0 + lr0, qg1 = q0 + lr1;

    // stage a 64x64 tile (hi+lo) of qkv columns [colbase, colbase+64)
    #define ISSUE_T(tile, bufoff, colbase) do {                                     \
        _Pragma("unroll")                                                           \
        for (int i_ = 0; i_ < 4; i_++) {                                            \
            int idx_ = tid + i_ * 256;                                              \
            int wh_ = idx_ >> 9, rr_ = (idx_ >> 3) & 63, cc_ = idx_ & 7;            \
            const __nv_bfloat16* src_ = (wh_ ? qkl : qkh) +                         \
                (size_t)(bT + (tile) * 64 + rr_) * 3072 + (colbase) + cc_ * 8;      \
            uint32_t dst_ = sb + (uint32_t)(bufoff) +                               \
                (uint32_t)(wh_ * 8192 + rr_ * 128 + ((cc_ ^ (rr_ & 7)) << 4));      \
            CPASYNC16(dst_, src_);                                                  \
        }                                                                           \
    } while (0)

    #define COMPUTE_S(sa, kbuf) do {                                                \
        _Pragma("unroll")                                                           \
        for (int k32_ = 0; k32_ < 2; k32_++) {                                      \
            _Pragma("unroll")                                                       \
            for (int nt_ = 0; nt_ < 4; nt_++) {                                     \
                int rk_ = cg * 32 + nt_ * 8 + (lane & 7);                           \
                int c16_ = k32_ * 4 + (lane >> 3);                                  \
                uint32_t ad_ = (kbuf) + (uint32_t)(rk_ * 128 + ((c16_ ^ (rk_ & 7)) << 4)); \
                uint32_t kh_[4], kl_[4];                                            \
                LDSM4(kh_[0], kh_[1], kh_[2], kh_[3], ad_);                         \
                LDSM4(kl_[0], kl_[1], kl_[2], kl_[3], ad_ + 8192);                  \
                uint32_t bh0_[2] = {kh_[0], kh_[1]}, bh1_[2] = {kh_[2], kh_[3]};    \
                uint32_t bl0_[2] = {kl_[0], kl_[1]}, bl1_[2] = {kl_[2], kl_[3]};    \
                MMA16816(sa[nt_], qfh[k32_*2],     bh0_);                           \
                MMA16816(sa[nt_], qfh[k32_*2],     bl0_);                           \
                MMA16816(sa[nt_], qfl[k32_*2],     bh0_);                           \
                MMA16816(sa[nt_], qfh[k32_*2 + 1], bh1_);                           \
                MMA16816(sa[nt_], qfh[k32_*2 + 1], bl1_);                           \
                MMA16816(sa[nt_], qfl[k32_*2 + 1], bh1_);                           \
            }                                                                       \
        }                                                                           \
    } while (0)

    // ---- Stage Q through stage-0 K slot; load fragments ----
    uint32_t qfh[4][4], qfl[4][4];
    ISSUE_T(q0 >> 6, 0, h * 64);
    CP_COMMIT(); CP_WAIT0();
    __syncthreads();
    #pragma unroll
    for (int c = 0; c < 4; c++) {
        int row = rg * 16 + (lane & 15);
        int c16 = c * 2 + (lane >> 4);
        uint32_t ad = sb + (uint32_t)(row * 128 + ((c16 ^ (row & 7)) << 4));
        LDSM4(qfh[c][0], qfh[c][1], qfh[c][2], qfh[c][3], ad);
        LDSM4(qfl[c][0], qfl[c][1], qfl[c][2], qfl[c][3], ad + 8192);
    }
    __syncthreads();

    // ---- zero tail of attn_w ----
    if (attw && kspan < TT) {
        float4 z = make_float4(0.f, 0.f, 0.f, 0.f);
        const int ntail4 = (TT - kspan) >> 2;
        float* wb = attw + ((size_t)(b * HH + h) * TT + q0) * TT;
        for (int i = tid; i < 64 * ntail4; i += 256) {
            int r = i / ntail4, c = i - r * ntail4;
            *(float4*)(wb + (size_t)r * TT + kspan + c * 4) = z;
        }
    }

    // ---- Pass A: l = sum exp(s) (no max; thread-local, no per-tile barriers) ----
    float l0 = 0.f, l1 = 0.f;

    ISSUE_T(0, 0, CC + h * 64); CP_COMMIT();
    if (ntiles > 1) { ISSUE_T(1, STG_SZ, CC + h * 64); CP_COMMIT(); }
    for (int t = 0; t < ntiles; t++) {
        if (t + 1 < ntiles) CP_WAIT1(); else CP_WAIT0();
        __syncthreads();
        if (t + 2 < ntiles) { ISSUE_T(t + 2, ((t + 2) % 3) * STG_SZ, CC + h * 64); CP_COMMIT(); }

        float sa[4][4] = {};
        COMPUTE_S(sa, sb + (uint32_t)(t % 3) * STG_SZ);

        #pragma unroll
        for (int nt = 0; nt < 4; nt++) {
            int j0 = t * 64 + cg * 32 + nt * 8 + (lane & 3) * 2;
            l0 += __expf((j0     <= qg0) ? sa[nt][0] * scale : -1e30f);
            l0 += __expf((j0 + 1 <= qg0) ? sa[nt][1] * scale : -1e30f);
            l1 += __expf((j0     <= qg1) ? sa[nt][2] * scale : -1e30f);
            l1 += __expf((j0 + 1 <= qg1) ? sa[nt][3] * scale : -1e30f);
        }
    }
    // reduce l across quad lanes + cg halves
    l0 += __shfl_xor_sync(0xffffffffu, l0, 1);
    l0 += __shfl_xor_sync(0xffffffffu, l0, 2);
    l1 += __shfl_xor_sync(0xffffffffu, l1, 1);
    l1 += __shfl_xor_sync(0xffffffffu, l1, 2);
    __syncthreads();   // all reads of K stage buffers done before reuse/ssum
    if ((lane & 3) == 0) { ssum[cg * 64 + lr0] = l0; ssum[cg * 64 + lr1] = l1; }
    __syncthreads();
    const float invl0 = 1.0f / (ssum[lr0] + ssum[64 + lr0]);
    const float invl1 = 1.0f / (ssum[lr1] + ssum[64 + lr1]);

    // ---- Pass B: recompute S, emit attn_w, PV accumulate ----
    float oa[8][4] = {};
    float* wrow0 = attw ? attw + (((size_t)(b * HH + h) * TT + qg0) * TT) : (float*)0;
    float* wrow1 = attw ? attw + (((size_t)(b * HH + h) * TT + qg1) * TT) : (float*)0;

    ISSUE_T(0, 0, CC + h * 64);
    ISSUE_T(0, 16384, 2 * CC + h * 64);
    CP_COMMIT();
    if (ntiles > 1) {
        ISSUE_T(1, STG_SZ, CC + h * 64);
        ISSUE_T(1, STG_SZ + 16384, 2 * CC + h * 64);
        CP_COMMIT();
    }
    for (int t = 0; t < ntiles; t++) {
        if (t + 1 < ntiles) CP_WAIT1(); else CP_WAIT0();
        __syncthreads();
        if (t + 2 < ntiles) {
            uint32_t st = (uint32_t)((t + 2) % 3) * STG_SZ;
            ISSUE_T(t + 2, st, CC + h * 64);
            ISSUE_T(t + 2, st + 16384, 2 * CC + h * 64);
            CP_COMMIT();
        }

        const uint32_t st = (uint32_t)(t % 3) * STG_SZ;
        float sa[4][4] = {};
        COMPUTE_S(sa, sb + st);

        float p[4][4];
        #pragma unroll
        for (int nt = 0; nt < 4; nt++) {
            int j0 = t * 64 + cg * 32 + nt * 8 + (lane & 3) * 2;
            p[nt][0] = (j0     <= qg0) ? __expf(sa[nt][0] * scale) * invl0 : 0.f;
            p[nt][1] = (j0 + 1 <= qg0) ? __expf(sa[nt][1] * scale) * invl0 : 0.f;
            p[nt][2] = (j0     <= qg1) ? __expf(sa[nt][2] * scale) * invl1 : 0.f;
            p[nt][3] = (j0 + 1 <= qg1) ? __expf(sa[nt][3] * scale) * invl1 : 0.f;
            if (wrow0) {
                *(float2*)(wrow0 + j0) = make_float2(p[nt][0], p[nt][1]);
                *(float2*)(wrow1 + j0) = make_float2(p[nt][2], p[nt][3]);
            }
        }

        uint32_t pah[2][4], pal[2][4];
        #pragma unroll
        for (int kb = 0; kb < 2; kb++) {
            pah[kb][0] = pack2bf(p[2*kb][0],   p[2*kb][1]);
            pah[kb][1] = pack2bf(p[2*kb][2],   p[2*kb][3]);
            pah[kb][2] = pack2bf(p[2*kb+1][0], p[2*kb+1][1]);
            pah[kb][3] = pack2bf(p[2*kb+1][2], p[2*kb+1][3]);
            pal[kb][0] = pack2bf(bf_res(p[2*kb][0]),   bf_res(p[2*kb][1]));
            pal[kb][1] = pack2bf(bf_res(p[2*kb][2]),   bf_res(p[2*kb][3]));
            pal[kb][2] = pack2bf(bf_res(p[2*kb+1][0]), bf_res(p[2*kb+1][1]));
            pal[kb][3] = pack2bf(bf_res(p[2*kb+1][2]), bf_res(p[2*kb+1][3]));
        }

        const uint32_t vbuf = sb + st + 16384;
        #pragma unroll
        for (int nd = 0; nd < 8; nd++) {
            int rv = cg * 32 + (lane >> 3) * 8 + (lane & 7);
            uint32_t ad = vbuf + (uint32_t)(rv * 128 + ((nd ^ (rv & 7)) << 4));
            uint32_t vh[4], vl[4];
            LDSM4T(vh[0], vh[1], vh[2], vh[3], ad);
            LDSM4T(vl[0], vl[1], vl[2], vl[3], ad + 8192);
            #pragma unroll
            for (int kb = 0; kb < 2; kb++) {
                uint32_t bvh[2] = {vh[kb*2], vh[kb*2+1]};
                uint32_t bvl[2] = {vl[kb*2], vl[kb*2+1]};
                MMA16816(oa[nd], pah[kb], bvh);
                MMA16816(oa[nd], pah[kb], bvl);
                MMA16816(oa[nd], pal[kb], bvh);
            }
        }
    }
    __syncthreads();   // all V reads done before ored reuse

    // ---- reduce col-group pairs, emit bf16 hi/lo ----
    float* ored = (float*)smem;   // 64 x 64 fp32 (reuses stage 0/1)
    if (cg == 1) {
        #pragma unroll
        for (int nd = 0; nd < 8; nd++) {
            int d0 = nd * 8 + (lane & 3) * 2;
            *(float2*)&ored[lr0 * 64 + d0] = make_float2(oa[nd][0], oa[nd][1]);
            *(float2*)&ored[lr1 * 64 + d0] = make_float2(oa[nd][2], oa[nd][3]);
        }
    }
    __syncthreads();
    if (cg == 0) {
        #pragma unroll
        for (int nd = 0; nd < 8; nd++) {
            int d0 = nd * 8 + (lane & 3) * 2;
            float2 q0v = *(float2*)&ored[lr0 * 64 + d0];
            float2 q1v = *(float2*)&ored[lr1 * 64 + d0];
            float a0 = oa[nd][0] + q0v.x, a1 = oa[nd][1] + q0v.y;
            float a2 = oa[nd][2] + q1v.x, a3 = oa[nd][3] + q1v.y;
            size_t r1 = (size_t)(bT + qg0) * CC + h * 64 + d0;
            size_t r2 = (size_t)(bT + qg1) * CC + h * 64 + d0;
            __nv_bfloat162 hh, ll;
            hh.x = __float2bfloat16(a0); hh.y = __float2bfloat16(a1);
            ll.x = __float2bfloat16(a0 - __bfloat162float(hh.x));
            ll.y = __float2bfloat16(a1 - __bfloat162float(hh.y));
            *(__nv_bfloat162*)&oh[r1] = hh; *(__nv_bfloat162*)&ol[r1] = ll;
            hh.x = __float2bfloat16(a2); hh.y = __float2bfloat16(a3);
            ll.x = __float2bfloat16(a2 - __bfloat162float(hh.x));
            ll.y = __float2bfloat16(a3 - __bfloat162float(hh.y));
            *(__nv_bfloat162*)&oh[r2] = hh; *(__nv_bfloat162*)&ol[r2] = ll;
        }
    }
    #undef ISSUE_T
    #undef COMPUTE_S
}

// ---------------------------------------------------------------------------
extern "C" void kernel_launch(void* const* d_in, const int* in_sizes, int n_in,
                              void* d_out, int out_size)
{
    (void)in_sizes; (void)n_in;
    const float* x     = (const float*)d_in[0];
    const float* w_qkv = (const float*)d_in[1];
    const float* b_qkv = (const float*)d_in[2];
    const float* w_o   = (const float*)d_in[3];
    const float* b_o   = (const float*)d_in[4];
    float* out = (float*)d_out;

    __nv_bfloat16 *xhi, *xlo, *w1hi, *w1lo, *w2hi, *w2lo, *qh, *ql, *ahi, *alo;
    cudaGetSymbolAddress((void**)&xhi, g_xhi);   cudaGetSymbolAddress((void**)&xlo, g_xlo);
    cudaGetSymbolAddress((void**)&w1hi, g_w1hi); cudaGetSymbolAddress((void**)&w1lo, g_w1lo);
    cudaGetSymbolAddress((void**)&w2hi, g_w2hi); cudaGetSymbolAddress((void**)&w2lo, g_w2lo);
    cudaGetSymbolAddress((void**)&qh, g_qh);     cudaGetSymbolAddress((void**)&ql, g_ql);
    cudaGetSymbolAddress((void**)&ahi, g_ahi);   cudaGetSymbolAddress((void**)&alo, g_alo);

    const int gemm_smem = 3 * 65536;
    cudaFuncSetAttribute(mma_gemm, cudaFuncAttributeMaxDynamicSharedMemorySize, gemm_smem);
    cudaFuncSetAttribute(attn_fa, cudaFuncAttributeMaxDynamicSharedMemorySize, ATTN_SMEM);

    // prep
    split_f32<<<(MM * CC + 1023) / 1024, 1024>>>(x, xhi, xlo, MM * CC);
    transpose_split<<<dim3(3 * CC / 32, CC / 32), dim3(32, 8)>>>(w_qkv, w1hi, w1lo, CC, 3 * CC);
    transpose_split<<<dim3(CC / 32, CC / 32), dim3(32, 8)>>>(w_o, w2hi, w2lo, CC, CC);

    // 1) QKV projection -> bf16 hi/lo
    mma_gemm<<<dim3(3 * CC / 128, MM / 128), 256, gemm_smem>>>(
        xhi, xlo, w1hi, w1lo, b_qkv, (float*)0, qh, ql, 3 * CC, CC);

    // 2) attention (two-pass flash, tensor cores)
    size_t o_elems = (size_t)MM * CC;
    float* attw = ((size_t)out_size > o_elems) ? out + o_elems : (float*)0;
    dim3 g2(TT / 64, HH, BB);
    attn_fa<<<g2, 256, ATTN_SMEM>>>(qh, ql, attw, ahi, alo);

    // 3) output projection
    mma_gemm<<<dim3(CC / 128, MM / 128), 256, gemm_smem>>>(
        ahi, alo, w2hi, w2lo, b_o, out, (__nv_bfloat16*)0, (__nv_bfloat16*)0, CC, CC);
}

// round 7
// speedup vs baseline: 6.0943x; 1.4452x over previous
#include <cuda_runtime.h>
#include <cuda_fp16.h>
#include <cstdint>

// Problem constants
#define BB 2
#define TT 2048
#define CC 1024
#define HH 16
#define DD 64
#define MM (BB*TT)   // 4096 rows

// Attention smem: 3 stages x 16KB (K hi 8KB | V hi 8KB), ssum after
#define STG_SZ   16384
#define OFF_SSUM 49152
#define ATTN_SMEM 49664

// GEMM smem: 2 stages x 48KB (Ah 16K | Al 16K | Bh 16K)
#define GSTG_SZ  49152
#define GEMM_SMEM (2 * GSTG_SZ)

// ---------------- scratch (no allocs allowed) ----------------
static __device__ __align__(128) __half g_xhi[(size_t)MM * CC], g_xlo[(size_t)MM * CC];
static __device__ __align__(128) __half g_w1h[(size_t)3 * CC * CC];
static __device__ __align__(128) __half g_w2h[(size_t)CC * CC];
static __device__ __align__(128) __half g_qh[(size_t)MM * 3 * CC], g_ql[(size_t)MM * 3 * CC];
static __device__ __align__(128) __half g_ahi[(size_t)MM * CC], g_alo[(size_t)MM * CC];

// ---------------- helpers ----------------
__device__ __forceinline__ uint32_t smem_u32(const void* p) {
    uint32_t a;
    asm("{ .reg .u64 t; cvta.to.shared.u64 t, %1; cvt.u32.u64 %0, t; }" : "=r"(a) : "l"(p));
    return a;
}

#define CPASYNC16(dst, src) \
    asm volatile("cp.async.cg.shared.global [%0], [%1], 16;" :: "r"(dst), "l"(src))
#define CP_COMMIT()  asm volatile("cp.async.commit_group;" ::: "memory")
#define CP_WAIT0()   asm volatile("cp.async.wait_group 0;" ::: "memory")
#define CP_WAIT1()   asm volatile("cp.async.wait_group 1;" ::: "memory")

#define LDSM4(r0, r1, r2, r3, addr) \
    asm volatile("ldmatrix.sync.aligned.m8n8.x4.shared.b16 {%0,%1,%2,%3}, [%4];" \
                 : "=r"(r0), "=r"(r1), "=r"(r2), "=r"(r3) : "r"(addr))

#define LDSM4T(r0, r1, r2, r3, addr) \
    asm volatile("ldmatrix.sync.aligned.m8n8.x4.trans.shared.b16 {%0,%1,%2,%3}, [%4];" \
                 : "=r"(r0), "=r"(r1), "=r"(r2), "=r"(r3) : "r"(addr))

#define MMA16816(d, a, b) \
    asm volatile("mma.sync.aligned.m16n8k16.row.col.f32.f16.f16.f32 " \
                 "{%0,%1,%2,%3}, {%4,%5,%6,%7}, {%8,%9}, {%0,%1,%2,%3};" \
                 : "+f"((d)[0]), "+f"((d)[1]), "+f"((d)[2]), "+f"((d)[3]) \
                 : "r"((a)[0]), "r"((a)[1]), "r"((a)[2]), "r"((a)[3]), \
                   "r"((b)[0]), "r"((b)[1]))

__device__ __forceinline__ uint32_t pack2h(float a, float b) {
    __half2 t;
    t.x = __float2half(a); t.y = __float2half(b);
    return *(uint32_t*)&t;
}
__device__ __forceinline__ float h_res(float v) {
    return v - __half2float(__float2half(v));
}

// ---------------------------------------------------------------------------
// prep kernels
// ---------------------------------------------------------------------------
__global__ void split_f32(const float* __restrict__ in, __half* __restrict__ hi,
                          __half* __restrict__ lo, int n) {
    int i = blockIdx.x * blockDim.x + threadIdx.x;
    if (i < n) {
        float v = in[i];
        __half h = __float2half(v);
        hi[i] = h;
        lo[i] = __float2half(v - __half2float(h));
    }
}

// w [K,N] f32 -> wT [N,K] fp16 (round)
__global__ void transpose_h(const float* __restrict__ w, __half* __restrict__ hi,
                            int K, int N) {
    __shared__ float t[32][33];
    int n0 = blockIdx.x * 32, k0 = blockIdx.y * 32;
    int tx = threadIdx.x, ty = threadIdx.y;
    #pragma unroll
    for (int j = 0; j < 32; j += 8)
        t[ty + j][tx] = w[(size_t)(k0 + ty + j) * N + n0 + tx];
    __syncthreads();
    #pragma unroll
    for (int j = 0; j < 32; j += 8)
        hi[(size_t)(n0 + ty + j) * K + k0 + tx] = __float2half(t[tx][ty + j]);
}

// ---------------------------------------------------------------------------
// fp16 2-pass GEMM: C[M,N] = (Ah+Al) @ Bh^T + bias   (Bh as [N,K] fp16)
// 128x128 tile, BK=64, 2-stage cp.async, 2 CTAs/SM.
// ---------------------------------------------------------------------------
__global__ __launch_bounds__(256, 2) void mma_gemm(
    const __half* __restrict__ Ahi, const __half* __restrict__ Alo,
    const __half* __restrict__ Bh, const float* __restrict__ bias,
    float* __restrict__ C, __half* __restrict__ Chi, __half* __restrict__ Clo,
    int N, int K)
{
    extern __shared__ char smem[];
    const uint32_t sb = smem_u32(smem);
    const int tid = threadIdx.x;
    const int lane = tid & 31, wid = tid >> 5;
    const int warpM = wid >> 2, warpN = wid & 3;
    const int m0 = blockIdx.y * 128, n0 = blockIdx.x * 128;

    const __half* pAh = Ahi + (size_t)m0 * K;
    const __half* pAl = Alo + (size_t)m0 * K;
    const __half* pBh = Bh + (size_t)n0 * K;

    float acc[4][4][4] = {};
    const int nch = K >> 6;

    #define STAGE_LOAD(stg, kc) do {                                              \
        uint32_t s0_ = sb + (uint32_t)(stg) * GSTG_SZ;                            \
        _Pragma("unroll")                                                         \
        for (int i_ = 0; i_ < 4; i_++) {                                          \
            int idx_ = tid + i_ * 256;                                            \
            int row_ = idx_ >> 3, c16_ = idx_ & 7;                                \
            uint32_t so_ = (uint32_t)(row_ * 128 + ((c16_ ^ (row_ & 7)) << 4));   \
            size_t go_ = (size_t)row_ * K + (kc) + c16_ * 8;                      \
            CPASYNC16(s0_ + so_,          pAh + go_);                             \
            CPASYNC16(s0_ + 16384 + so_,  pAl + go_);                             \
            CPASYNC16(s0_ + 32768 + so_,  pBh + go_);                             \
        }                                                                         \
        CP_COMMIT();                                                              \
    } while (0)

    STAGE_LOAD(0, 0);

    for (int c = 0; c < nch; c++) {
        CP_WAIT0();
        __syncthreads();
        if (c + 1 < nch) STAGE_LOAD((c + 1) & 1, (c + 1) * 64);

        const uint32_t aB = sb + (uint32_t)(c & 1) * GSTG_SZ;
        const uint32_t bB = aB + 32768;

        #pragma unroll
        for (int k16 = 0; k16 < 4; k16++) {
            uint32_t ah[4][4], al[4][4], bh[4][2];
            #pragma unroll
            for (int mi = 0; mi < 4; mi++) {
                int row = warpM * 64 + mi * 16 + (lane & 15);
                int c16 = k16 * 2 + (lane >> 4);
                uint32_t ad = aB + (uint32_t)(row * 128 + ((c16 ^ (row & 7)) << 4));
                LDSM4(ah[mi][0], ah[mi][1], ah[mi][2], ah[mi][3], ad);
                LDSM4(al[mi][0], al[mi][1], al[mi][2], al[mi][3], ad + 16384);
            }
            #pragma unroll
            for (int p = 0; p < 2; p++) {
                int g = lane >> 3, r = lane & 7;
                int row = warpN * 32 + p * 16 + (g >> 1) * 8 + r;
                int c16 = k16 * 2 + (g & 1);
                uint32_t bd = bB + (uint32_t)(row * 128 + ((c16 ^ (row & 7)) << 4));
                uint32_t t0, t1, t2, t3;
                LDSM4(t0, t1, t2, t3, bd);
                bh[2*p][0] = t0; bh[2*p][1] = t1; bh[2*p+1][0] = t2; bh[2*p+1][1] = t3;
            }
            #pragma unroll
            for (int mi = 0; mi < 4; mi++)
                #pragma unroll
                for (int ni = 0; ni < 4; ni++) {
                    MMA16816(acc[mi][ni], ah[mi], bh[ni]);
                    MMA16816(acc[mi][ni], al[mi], bh[ni]);
                }
        }
        __syncthreads();
    }

    #pragma unroll
    for (int mi = 0; mi < 4; mi++) {
        int row = m0 + warpM * 64 + mi * 16 + (lane >> 2);
        #pragma unroll
        for (int ni = 0; ni < 4; ni++) {
            int col = n0 + warpN * 32 + ni * 8 + (lane & 3) * 2;
            float b0 = bias[col], b1 = bias[col + 1];
            float v00 = acc[mi][ni][0] + b0, v01 = acc[mi][ni][1] + b1;
            float v10 = acc[mi][ni][2] + b0, v11 = acc[mi][ni][3] + b1;
            if (Chi) {
                __half2 hh, ll;
                hh.x = __float2half(v00); hh.y = __float2half(v01);
                ll.x = __float2half(v00 - __half2float(hh.x));
                ll.y = __float2half(v01 - __half2float(hh.y));
                *(__half2*)&Chi[(size_t)row * N + col] = hh;
                *(__half2*)&Clo[(size_t)row * N + col] = ll;
                hh.x = __float2half(v10); hh.y = __float2half(v11);
                ll.x = __float2half(v10 - __half2float(hh.x));
                ll.y = __float2half(v11 - __half2float(hh.y));
                *(__half2*)&Chi[(size_t)(row + 8) * N + col] = hh;
                *(__half2*)&Clo[(size_t)(row + 8) * N + col] = ll;
            } else {
                *(float2*)&C[(size_t)row * N + col] = make_float2(v00, v01);
                *(float2*)&C[(size_t)(row + 8) * N + col] = make_float2(v10, v11);
            }
        }
    }
    #undef STAGE_LOAD
}

// ---------------------------------------------------------------------------
// Two-pass flash attention, TQ=64, fp16 2-pass MMA, no running max.
// ---------------------------------------------------------------------------
__global__ __launch_bounds__(256, 2) void attn_fa(
    const __half* __restrict__ qkh, const __half* __restrict__ qkl,
    float* __restrict__ attw,
    __half* __restrict__ oh, __half* __restrict__ ol)
{
    extern __shared__ char smem[];
    const uint32_t sb = smem_u32(smem);
    float* ssum = (float*)(smem + OFF_SSUM);
    const int tid = threadIdx.x, lane = tid & 31, wid = tid >> 5;
    const int rg = wid >> 1, cg = wid & 1;
    const int q0 = (int)(gridDim.x - 1 - blockIdx.x) * 64;   // big blocks first
    const int h  = blockIdx.y;
    const int b  = blockIdx.z;
    const int bT = b * TT;
    const int ntiles = (q0 >> 6) + 1;
    const int kspan  = ntiles * 64;
    const float scale = 0.125f;

    const int lr0 = rg * 16 + (lane >> 2);
    const int lr1 = lr0 + 8;
    const int qg0 = q0 + lr0, qg1 = q0 + lr1;

    // stage a 64x64 fp16 tile (hi only) of qkv columns [colbase, colbase+64)
    #define ISSUE_H(tile, bufoff, colbase) do {                                     \
        _Pragma("unroll")                                                           \
        for (int i_ = 0; i_ < 2; i_++) {                                            \
            int idx_ = tid + i_ * 256;                                              \
            int rr_ = idx_ >> 3, cc_ = idx_ & 7;                                    \
            const __half* src_ = qkh +                                              \
                (size_t)(bT + (tile) * 64 + rr_) * 3072 + (colbase) + cc_ * 8;      \
            uint32_t dst_ = sb + (uint32_t)(bufoff) +                               \
                (uint32_t)(rr_ * 128 + ((cc_ ^ (rr_ & 7)) << 4));                   \
            CPASYNC16(dst_, src_);                                                  \
        }                                                                           \
    } while (0)

    #define COMPUTE_S(sa, kbuf) do {                                                \
        _Pragma("unroll")                                                           \
        for (int k32_ = 0; k32_ < 2; k32_++) {                                      \
            _Pragma("unroll")                                                       \
            for (int nt_ = 0; nt_ < 4; nt_++) {                                     \
                int rk_ = cg * 32 + nt_ * 8 + (lane & 7);                           \
                int c16_ = k32_ * 4 + (lane >> 3);                                  \
                uint32_t ad_ = (kbuf) + (uint32_t)(rk_ * 128 + ((c16_ ^ (rk_ & 7)) << 4)); \
                uint32_t kh_[4];                                                    \
                LDSM4(kh_[0], kh_[1], kh_[2], kh_[3], ad_);                         \
                uint32_t bh0_[2] = {kh_[0], kh_[1]}, bh1_[2] = {kh_[2], kh_[3]};    \
                MMA16816(sa[nt_], qfh[k32_*2],     bh0_);                           \
                MMA16816(sa[nt_], qfl[k32_*2],     bh0_);                           \
                MMA16816(sa[nt_], qfh[k32_*2 + 1], bh1_);                           \
                MMA16816(sa[nt_], qfl[k32_*2 + 1], bh1_);                           \
            }                                                                       \
        }                                                                           \
    } while (0)

    // ---- Stage Q (hi @0, lo @8192); load fragments ----
    uint32_t qfh[4][4], qfl[4][4];
    {
        #pragma unroll
        for (int i_ = 0; i_ < 4; i_++) {
            int idx_ = tid + i_ * 256;
            int wh_ = idx_ >> 9, rr_ = (idx_ >> 3) & 63, cc_ = idx_ & 7;
            const __half* src_ = (wh_ ? qkl : qkh) +
                (size_t)(bT + q0 + rr_) * 3072 + h * 64 + cc_ * 8;
            uint32_t dst_ = sb + (uint32_t)(wh_ * 8192 + rr_ * 128 + ((cc_ ^ (rr_ & 7)) << 4));
            CPASYNC16(dst_, src_);
        }
        CP_COMMIT(); CP_WAIT0();
        __syncthreads();
        #pragma unroll
        for (int c = 0; c < 4; c++) {
            int row = rg * 16 + (lane & 15);
            int c16 = c * 2 + (lane >> 4);
            uint32_t ad = sb + (uint32_t)(row * 128 + ((c16 ^ (row & 7)) << 4));
            LDSM4(qfh[c][0], qfh[c][1], qfh[c][2], qfh[c][3], ad);
            LDSM4(qfl[c][0], qfl[c][1], qfl[c][2], qfl[c][3], ad + 8192);
        }
        __syncthreads();
    }

    // ---- zero tail of attn_w ----
    if (attw && kspan < TT) {
        float4 z = make_float4(0.f, 0.f, 0.f, 0.f);
        const int ntail4 = (TT - kspan) >> 2;
        float* wb = attw + ((size_t)(b * HH + h) * TT + q0) * TT;
        for (int i = tid; i < 64 * ntail4; i += 256) {
            int r = i / ntail4, c = i - r * ntail4;
            *(float4*)(wb + (size_t)r * TT + kspan + c * 4) = z;
        }
    }

    // ---- Pass A: l = sum exp(s), K tiles only ----
    float l0 = 0.f, l1 = 0.f;

    ISSUE_H(0, 0, CC + h * 64); CP_COMMIT();
    if (ntiles > 1) { ISSUE_H(1, STG_SZ, CC + h * 64); CP_COMMIT(); }
    for (int t = 0; t < ntiles; t++) {
        if (t + 1 < ntiles) CP_WAIT1(); else CP_WAIT0();
        __syncthreads();
        if (t + 2 < ntiles) { ISSUE_H(t + 2, ((t + 2) % 3) * STG_SZ, CC + h * 64); CP_COMMIT(); }

        float sa[4][4] = {};
        COMPUTE_S(sa, sb + (uint32_t)(t % 3) * STG_SZ);

        #pragma unroll
        for (int nt = 0; nt < 4; nt++) {
            int j0 = t * 64 + cg * 32 + nt * 8 + (lane & 3) * 2;
            l0 += __expf((j0     <= qg0) ? sa[nt][0] * scale : -1e30f);
            l0 += __expf((j0 + 1 <= qg0) ? sa[nt][1] * scale : -1e30f);
            l1 += __expf((j0     <= qg1) ? sa[nt][2] * scale : -1e30f);
            l1 += __expf((j0 + 1 <= qg1) ? sa[nt][3] * scale : -1e30f);
        }
    }
    l0 += __shfl_xor_sync(0xffffffffu, l0, 1);
    l0 += __shfl_xor_sync(0xffffffffu, l0, 2);
    l1 += __shfl_xor_sync(0xffffffffu, l1, 1);
    l1 += __shfl_xor_sync(0xffffffffu, l1, 2);
    __syncthreads();
    if ((lane & 3) == 0) { ssum[cg * 64 + lr0] = l0; ssum[cg * 64 + lr1] = l1; }
    __syncthreads();
    const float invl0 = 1.0f / (ssum[lr0] + ssum[64 + lr0]);
    const float invl1 = 1.0f / (ssum[lr1] + ssum[64 + lr1]);

    // ---- Pass B: recompute S, emit attn_w, PV ----
    float oa[8][4] = {};
    float* wrow0 = attw ? attw + (((size_t)(b * HH + h) * TT + qg0) * TT) : (float*)0;
    float* wrow1 = attw ? attw + (((size_t)(b * HH + h) * TT + qg1) * TT) : (float*)0;

    ISSUE_H(0, 0, CC + h * 64);
    ISSUE_H(0, 8192, 2 * CC + h * 64);
    CP_COMMIT();
    if (ntiles > 1) {
        ISSUE_H(1, STG_SZ, CC + h * 64);
        ISSUE_H(1, STG_SZ + 8192, 2 * CC + h * 64);
        CP_COMMIT();
    }
    for (int t = 0; t < ntiles; t++) {
        if (t + 1 < ntiles) CP_WAIT1(); else CP_WAIT0();
        __syncthreads();
        if (t + 2 < ntiles) {
            uint32_t st = (uint32_t)((t + 2) % 3) * STG_SZ;
            ISSUE_H(t + 2, st, CC + h * 64);
            ISSUE_H(t + 2, st + 8192, 2 * CC + h * 64);
            CP_COMMIT();
        }

        const uint32_t st = (uint32_t)(t % 3) * STG_SZ;
        float sa[4][4] = {};
        COMPUTE_S(sa, sb + st);

        float p[4][4];
        #pragma unroll
        for (int nt = 0; nt < 4; nt++) {
            int j0 = t * 64 + cg * 32 + nt * 8 + (lane & 3) * 2;
            p[nt][0] = (j0     <= qg0) ? __expf(sa[nt][0] * scale) * invl0 : 0.f;
            p[nt][1] = (j0 + 1 <= qg0) ? __expf(sa[nt][1] * scale) * invl0 : 0.f;
            p[nt][2] = (j0     <= qg1) ? __expf(sa[nt][2] * scale) * invl1 : 0.f;
            p[nt][3] = (j0 + 1 <= qg1) ? __expf(sa[nt][3] * scale) * invl1 : 0.f;
            if (wrow0) {
                *(float2*)(wrow0 + j0) = make_float2(p[nt][0], p[nt][1]);
                *(float2*)(wrow1 + j0) = make_float2(p[nt][2], p[nt][3]);
            }
        }

        uint32_t pah[2][4], pal[2][4];
        #pragma unroll
        for (int kb = 0; kb < 2; kb++) {
            pah[kb][0] = pack2h(p[2*kb][0],   p[2*kb][1]);
            pah[kb][1] = pack2h(p[2*kb][2],   p[2*kb][3]);
            pah[kb][2] = pack2h(p[2*kb+1][0], p[2*kb+1][1]);
            pah[kb][3] = pack2h(p[2*kb+1][2], p[2*kb+1][3]);
            pal[kb][0] = pack2h(h_res(p[2*kb][0]),   h_res(p[2*kb][1]));
            pal[kb][1] = pack2h(h_res(p[2*kb][2]),   h_res(p[2*kb][3]));
            pal[kb][2] = pack2h(h_res(p[2*kb+1][0]), h_res(p[2*kb+1][1]));
            pal[kb][3] = pack2h(h_res(p[2*kb+1][2]), h_res(p[2*kb+1][3]));
        }

        const uint32_t vbuf = sb + st + 8192;
        #pragma unroll
        for (int nd = 0; nd < 8; nd++) {
            int rv = cg * 32 + (lane >> 3) * 8 + (lane & 7);
            uint32_t ad = vbuf + (uint32_t)(rv * 128 + ((nd ^ (rv & 7)) << 4));
            uint32_t vh[4];
            LDSM4T(vh[0], vh[1], vh[2], vh[3], ad);
            #pragma unroll
            for (int kb = 0; kb < 2; kb++) {
                uint32_t bvh[2] = {vh[kb*2], vh[kb*2+1]};
                MMA16816(oa[nd], pah[kb], bvh);
                MMA16816(oa[nd], pal[kb], bvh);
            }
        }
    }
    __syncthreads();

    // ---- reduce col-group pairs, emit fp16 hi/lo ----
    float* ored = (float*)smem;   // 64 x 64 fp32 (reuses stages)
    if (cg == 1) {
        #pragma unroll
        for (int nd = 0; nd < 8; nd++) {
            int d0 = nd * 8 + (lane & 3) * 2;
            *(float2*)&ored[lr0 * 64 + d0] = make_float2(oa[nd][0], oa[nd][1]);
            *(float2*)&ored[lr1 * 64 + d0] = make_float2(oa[nd][2], oa[nd][3]);
        }
    }
    __syncthreads();
    if (cg == 0) {
        #pragma unroll
        for (int nd = 0; nd < 8; nd++) {
            int d0 = nd * 8 + (lane & 3) * 2;
            float2 q0v = *(float2*)&ored[lr0 * 64 + d0];
            float2 q1v = *(float2*)&ored[lr1 * 64 + d0];
            float a0 = oa[nd][0] + q0v.x, a1 = oa[nd][1] + q0v.y;
            float a2 = oa[nd][2] + q1v.x, a3 = oa[nd][3] + q1v.y;
            size_t r1 = (size_t)(bT + qg0) * CC + h * 64 + d0;
            size_t r2 = (size_t)(bT + qg1) * CC + h * 64 + d0;
            __half2 hh, ll;
            hh.x = __float2half(a0); hh.y = __float2half(a1);
            ll.x = __float2half(a0 - __half2float(hh.x));
            ll.y = __float2half(a1 - __half2float(hh.y));
            *(__half2*)&oh[r1] = hh; *(__half2*)&ol[r1] = ll;
            hh.x = __float2half(a2); hh.y = __float2half(a3);
            ll.x = __float2half(a2 - __half2float(hh.x));
            ll.y = __float2half(a3 - __half2float(hh.y));
            *(__half2*)&oh[r2] = hh; *(__half2*)&ol[r2] = ll;
        }
    }
    #undef ISSUE_H
    #undef COMPUTE_S
}

// ---------------------------------------------------------------------------
extern "C" void kernel_launch(void* const* d_in, const int* in_sizes, int n_in,
                              void* d_out, int out_size)
{
    (void)in_sizes; (void)n_in;
    const float* x     = (const float*)d_in[0];
    const float* w_qkv = (const float*)d_in[1];
    const float* b_qkv = (const float*)d_in[2];
    const float* w_o   = (const float*)d_in[3];
    const float* b_o   = (const float*)d_in[4];
    float* out = (float*)d_out;

    __half *xhi, *xlo, *w1h, *w2h, *qh, *ql, *ahi, *alo;
    cudaGetSymbolAddress((void**)&xhi, g_xhi); cudaGetSymbolAddress((void**)&xlo, g_xlo);
    cudaGetSymbolAddress((void**)&w1h, g_w1h); cudaGetSymbolAddress((void**)&w2h, g_w2h);
    cudaGetSymbolAddress((void**)&qh, g_qh);   cudaGetSymbolAddress((void**)&ql, g_ql);
    cudaGetSymbolAddress((void**)&ahi, g_ahi); cudaGetSymbolAddress((void**)&alo, g_alo);

    cudaFuncSetAttribute(mma_gemm, cudaFuncAttributeMaxDynamicSharedMemorySize, GEMM_SMEM);
    cudaFuncSetAttribute(attn_fa, cudaFuncAttributeMaxDynamicSharedMemorySize, ATTN_SMEM);

    // prep
    split_f32<<<(MM * CC + 1023) / 1024, 1024>>>(x, xhi, xlo, MM * CC);
    transpose_h<<<dim3(3 * CC / 32, CC / 32), dim3(32, 8)>>>(w_qkv, w1h, CC, 3 * CC);
    transpose_h<<<dim3(CC / 32, CC / 32), dim3(32, 8)>>>(w_o, w2h, CC, CC);

    // 1) QKV projection -> fp16 hi/lo
    mma_gemm<<<dim3(3 * CC / 128, MM / 128), 256, GEMM_SMEM>>>(
        xhi, xlo, w1h, b_qkv, (float*)0, qh, ql, 3 * CC, CC);

    // 2) attention
    size_t o_elems = (size_t)MM * CC;
    float* attw = ((size_t)out_size > o_elems) ? out + o_elems : (float*)0;
    dim3 g2(TT / 64, HH, BB);
    attn_fa<<<g2, 256, ATTN_SMEM>>>(qh, ql, attw, ahi, alo);

    // 3) output projection
    mma_gemm<<<dim3(CC / 128, MM / 128), 256, GEMM_SMEM>>>(
        ahi, alo, w2h, b_o, out, (__half*)0, (__half*)0, CC, CC);
}

// round 9
// speedup vs baseline: 6.5484x; 1.0745x over previous
#include <cuda_runtime.h>
#include <cuda_fp16.h>
#include <cstdint>

// Problem constants
#define BB 2
#define TT 2048
#define CC 1024
#define HH 16
#define DD 64
#define MM (BB*TT)   // 4096 rows

// Attention smem: 3 stages x 16KB (K hi 8KB | V hi 8KB), ssum after
#define STG_SZ   16384
#define OFF_SSUM 49152
#define ATTN_SMEM 49664

// GEMM smem: 2 stages x 48KB (Ah 16K | Al 16K | Bh 16K)
#define GSTG_SZ  49152
#define GEMM_SMEM (2 * GSTG_SZ)

// ---------------- scratch (no allocs allowed) ----------------
static __device__ __align__(128) __half g_xhi[(size_t)MM * CC], g_xlo[(size_t)MM * CC];
static __device__ __align__(128) __half g_w1h[(size_t)3 * CC * CC];
static __device__ __align__(128) __half g_w2h[(size_t)CC * CC];
static __device__ __align__(128) __half g_qh[(size_t)MM * 3 * CC], g_ql[(size_t)MM * 3 * CC];
static __device__ __align__(128) __half g_ahi[(size_t)MM * CC];

// ---------------- helpers ----------------
__device__ __forceinline__ uint32_t smem_u32(const void* p) {
    uint32_t a;
    asm("{ .reg .u64 t; cvta.to.shared.u64 t, %1; cvt.u32.u64 %0, t; }" : "=r"(a) : "l"(p));
    return a;
}

#define CPASYNC16(dst, src) \
    asm volatile("cp.async.cg.shared.global [%0], [%1], 16;" :: "r"(dst), "l"(src))
#define CP_COMMIT()  asm volatile("cp.async.commit_group;" ::: "memory")
#define CP_WAIT0()   asm volatile("cp.async.wait_group 0;" ::: "memory")
#define CP_WAIT1()   asm volatile("cp.async.wait_group 1;" ::: "memory")

#define LDSM4(r0, r1, r2, r3, addr) \
    asm volatile("ldmatrix.sync.aligned.m8n8.x4.shared.b16 {%0,%1,%2,%3}, [%4];" \
                 : "=r"(r0), "=r"(r1), "=r"(r2), "=r"(r3) : "r"(addr))

#define LDSM4T(r0, r1, r2, r3, addr) \
    asm volatile("ldmatrix.sync.aligned.m8n8.x4.trans.shared.b16 {%0,%1,%2,%3}, [%4];" \
                 : "=r"(r0), "=r"(r1), "=r"(r2), "=r"(r3) : "r"(addr))

#define MMA16816(d, a, b) \
    asm volatile("mma.sync.aligned.m16n8k16.row.col.f32.f16.f16.f32 " \
                 "{%0,%1,%2,%3}, {%4,%5,%6,%7}, {%8,%9}, {%0,%1,%2,%3};" \
                 : "+f"((d)[0]), "+f"((d)[1]), "+f"((d)[2]), "+f"((d)[3]) \
                 : "r"((a)[0]), "r"((a)[1]), "r"((a)[2]), "r"((a)[3]), \
                   "r"((b)[0]), "r"((b)[1]))

__device__ __forceinline__ uint32_t pack2h(float a, float b) {
    __half2 t;
    t.x = __float2half(a); t.y = __float2half(b);
    return *(uint32_t*)&t;
}

// ---------------------------------------------------------------------------
// prep kernels
// ---------------------------------------------------------------------------
__global__ void split_f32(const float* __restrict__ in, __half* __restrict__ hi,
                          __half* __restrict__ lo, int n) {
    int i = blockIdx.x * blockDim.x + threadIdx.x;
    if (i < n) {
        float v = in[i];
        __half h = __float2half(v);
        hi[i] = h;
        lo[i] = __float2half(v - __half2float(h));
    }
}

// w [K,N] f32 -> wT [N,K] fp16 (round)
__global__ void transpose_h(const float* __restrict__ w, __half* __restrict__ hi,
                            int K, int N) {
    __shared__ float t[32][33];
    int n0 = blockIdx.x * 32, k0 = blockIdx.y * 32;
    int tx = threadIdx.x, ty = threadIdx.y;
    #pragma unroll
    for (int j = 0; j < 32; j += 8)
        t[ty + j][tx] = w[(size_t)(k0 + ty + j) * N + n0 + tx];
    __syncthreads();
    #pragma unroll
    for (int j = 0; j < 32; j += 8)
        hi[(size_t)(n0 + ty + j) * K + k0 + tx] = __float2half(t[tx][ty + j]);
}

// ---------------------------------------------------------------------------
// fp16 GEMM: C[M,N] = (Ah [+Al if n0<lo_lim]) @ Bh^T + bias   (Bh as [N,K])
// 128x128 tile, BK=64, 2-stage cp.async, 2 CTAs/SM.
// Output: fp32 C, or fp16 Chi (+Clo for columns < lo_lim).
// ---------------------------------------------------------------------------
__global__ __launch_bounds__(256, 2) void mma_gemm(
    const __half* __restrict__ Ahi, const __half* __restrict__ Alo,
    const __half* __restrict__ Bh, const float* __restrict__ bias,
    float* __restrict__ C, __half* __restrict__ Chi, __half* __restrict__ Clo,
    int N, int K, int lo_lim)
{
    extern __shared__ char smem[];
    const uint32_t sb = smem_u32(smem);
    const int tid = threadIdx.x;
    const int lane = tid & 31, wid = tid >> 5;
    const int warpM = wid >> 2, warpN = wid & 3;
    const int m0 = blockIdx.y * 128, n0 = blockIdx.x * 128;
    const bool two_pass = (n0 < lo_lim);

    const __half* pAh = Ahi + (size_t)m0 * K;
    const __half* pAl = Alo + (size_t)m0 * K;
    const __half* pBh = Bh + (size_t)n0 * K;

    float acc[4][4][4] = {};
    const int nch = K >> 6;

    #define STAGE_LOAD(stg, kc) do {                                              \
        uint32_t s0_ = sb + (uint32_t)(stg) * GSTG_SZ;                            \
        _Pragma("unroll")                                                         \
        for (int i_ = 0; i_ < 4; i_++) {                                          \
            int idx_ = tid + i_ * 256;                                            \
            int row_ = idx_ >> 3, c16_ = idx_ & 7;                                \
            uint32_t so_ = (uint32_t)(row_ * 128 + ((c16_ ^ (row_ & 7)) << 4));   \
            size_t go_ = (size_t)row_ * K + (kc) + c16_ * 8;                      \
            CPASYNC16(s0_ + so_,          pAh + go_);                             \
            if (two_pass) CPASYNC16(s0_ + 16384 + so_, pAl + go_);                \
            CPASYNC16(s0_ + 32768 + so_,  pBh + go_);                             \
        }                                                                         \
        CP_COMMIT();                                                              \
    } while (0)

    STAGE_LOAD(0, 0);

    for (int c = 0; c < nch; c++) {
        CP_WAIT0();
        __syncthreads();
        if (c + 1 < nch) STAGE_LOAD((c + 1) & 1, (c + 1) * 64);

        const uint32_t aB = sb + (uint32_t)(c & 1) * GSTG_SZ;
        const uint32_t bB = aB + 32768;

        #pragma unroll
        for (int k16 = 0; k16 < 4; k16++) {
            uint32_t ah[4][4], al[4][4], bh[4][2];
            #pragma unroll
            for (int mi = 0; mi < 4; mi++) {
                int row = warpM * 64 + mi * 16 + (lane & 15);
                int c16 = k16 * 2 + (lane >> 4);
                uint32_t ad = aB + (uint32_t)(row * 128 + ((c16 ^ (row & 7)) << 4));
                LDSM4(ah[mi][0], ah[mi][1], ah[mi][2], ah[mi][3], ad);
                if (two_pass) LDSM4(al[mi][0], al[mi][1], al[mi][2], al[mi][3], ad + 16384);
            }
            #pragma unroll
            for (int p = 0; p < 2; p++) {
                int g = lane >> 3, r = lane & 7;
                int row = warpN * 32 + p * 16 + (g >> 1) * 8 + r;
                int c16 = k16 * 2 + (g & 1);
                uint32_t bd = bB + (uint32_t)(row * 128 + ((c16 ^ (row & 7)) << 4));
                uint32_t t0, t1, t2, t3;
                LDSM4(t0, t1, t2, t3, bd);
                bh[2*p][0] = t0; bh[2*p][1] = t1; bh[2*p+1][0] = t2; bh[2*p+1][1] = t3;
            }
            #pragma unroll
            for (int mi = 0; mi < 4; mi++)
                #pragma unroll
                for (int ni = 0; ni < 4; ni++) {
                    MMA16816(acc[mi][ni], ah[mi], bh[ni]);
                    if (two_pass) MMA16816(acc[mi][ni], al[mi], bh[ni]);
                }
        }
        __syncthreads();
    }

    #pragma unroll
    for (int mi = 0; mi < 4; mi++) {
        int row = m0 + warpM * 64 + mi * 16 + (lane >> 2);
        #pragma unroll
        for (int ni = 0; ni < 4; ni++) {
            int col = n0 + warpN * 32 + ni * 8 + (lane & 3) * 2;
            float b0 = bias[col], b1 = bias[col + 1];
            float v00 = acc[mi][ni][0] + b0, v01 = acc[mi][ni][1] + b1;
            float v10 = acc[mi][ni][2] + b0, v11 = acc[mi][ni][3] + b1;
            if (Chi) {
                uint32_t h0 = pack2h(v00, v01);
                uint32_t h1 = pack2h(v10, v11);
                *(uint32_t*)&Chi[(size_t)row * N + col] = h0;
                *(uint32_t*)&Chi[(size_t)(row + 8) * N + col] = h1;
                if (two_pass) {
                    __half2 hh0 = *(__half2*)&h0, hh1 = *(__half2*)&h1;
                    uint32_t l0 = pack2h(v00 - __half2float(hh0.x), v01 - __half2float(hh0.y));
                    uint32_t l1 = pack2h(v10 - __half2float(hh1.x), v11 - __half2float(hh1.y));
                    *(uint32_t*)&Clo[(size_t)row * N + col] = l0;
                    *(uint32_t*)&Clo[(size_t)(row + 8) * N + col] = l1;
                }
            } else {
                *(float2*)&C[(size_t)row * N + col] = make_float2(v00, v01);
                *(float2*)&C[(size_t)(row + 8) * N + col] = make_float2(v10, v11);
            }
        }
    }
    #undef STAGE_LOAD
}

// ---------------------------------------------------------------------------
// Two-pass flash attention, TQ=64, fp16 arithmetic, no running max.
// S: Q hi/lo x K hi (2-pass). PV: P hi x V hi (1-pass). Output hi fp16 only.
// ---------------------------------------------------------------------------
__global__ __launch_bounds__(256, 2) void attn_fa(
    const __half* __restrict__ qkh, const __half* __restrict__ qkl,
    float* __restrict__ attw, __half* __restrict__ oh)
{
    extern __shared__ char smem[];
    const uint32_t sb = smem_u32(smem);
    float* ssum = (float*)(smem + OFF_SSUM);
    const int tid = threadIdx.x, lane = tid & 31, wid = tid >> 5;
    const int rg = wid >> 1, cg = wid & 1;
    const int q0 = (int)(gridDim.x - 1 - blockIdx.x) * 64;   // big blocks first
    const int h  = blockIdx.y;
    const int b  = blockIdx.z;
    const int bT = b * TT;
    const int ntiles = (q0 >> 6) + 1;
    const int kspan  = ntiles * 64;
    const float scale = 0.125f;

    const int lr0 = rg * 16 + (lane >> 2);
    const int lr1 = lr0 + 8;
    const int qg0 = q0 + lr0, qg1 = q0 + lr1;

    #define ISSUE_H(tile, bufoff, colbase) do {                                     \
        _Pragma("unroll")                                                           \
        for (int i_ = 0; i_ < 2; i_++) {                                            \
            int idx_ = tid + i_ * 256;                                              \
            int rr_ = idx_ >> 3, cc_ = idx_ & 7;                                    \
            const __half* src_ = qkh +                                              \
                (size_t)(bT + (tile) * 64 + rr_) * 3072 + (colbase) + cc_ * 8;      \
            uint32_t dst_ = sb + (uint32_t)(bufoff) +                               \
                (uint32_t)(rr_ * 128 + ((cc_ ^ (rr_ & 7)) << 4));                   \
            CPASYNC16(dst_, src_);                                                  \
        }                                                                           \
    } while (0)

    #define COMPUTE_S(sa, kbuf) do {                                                \
        _Pragma("unroll")                                                           \
        for (int k32_ = 0; k32_ < 2; k32_++) {                                      \
            _Pragma("unroll")                                                       \
            for (int nt_ = 0; nt_ < 4; nt_++) {                                     \
                int rk_ = cg * 32 + nt_ * 8 + (lane & 7);                           \
                int c16_ = k32_ * 4 + (lane >> 3);                                  \
                uint32_t ad_ = (kbuf) + (uint32_t)(rk_ * 128 + ((c16_ ^ (rk_ & 7)) << 4)); \
                uint32_t kh_[4];                                                    \
                LDSM4(kh_[0], kh_[1], kh_[2], kh_[3], ad_);                         \
                uint32_t bh0_[2] = {kh_[0], kh_[1]}, bh1_[2] = {kh_[2], kh_[3]};    \
                MMA16816(sa[nt_], qfh[k32_*2],     bh0_);                           \
                MMA16816(sa[nt_], qfl[k32_*2],     bh0_);                           \
                MMA16816(sa[nt_], qfh[k32_*2 + 1], bh1_);                           \
                MMA16816(sa[nt_], qfl[k32_*2 + 1], bh1_);                           \
            }                                                                       \
        }                                                                           \
    } while (0)

    // ---- Stage Q (hi @0, lo @8192); load fragments ----
    uint32_t qfh[4][4], qfl[4][4];
    {
        #pragma unroll
        for (int i_ = 0; i_ < 4; i_++) {
            int idx_ = tid + i_ * 256;
            int wh_ = idx_ >> 9, rr_ = (idx_ >> 3) & 63, cc_ = idx_ & 7;
            const __half* src_ = (wh_ ? qkl : qkh) +
                (size_t)(bT + q0 + rr_) * 3072 + h * 64 + cc_ * 8;
            uint32_t dst_ = sb + (uint32_t)(wh_ * 8192 + rr_ * 128 + ((cc_ ^ (rr_ & 7)) << 4));
            CPASYNC16(dst_, src_);
        }
        CP_COMMIT(); CP_WAIT0();
        __syncthreads();
        #pragma unroll
        for (int c = 0; c < 4; c++) {
            int row = rg * 16 + (lane & 15);
            int c16 = c * 2 + (lane >> 4);
            uint32_t ad = sb + (uint32_t)(row * 128 + ((c16 ^ (row & 7)) << 4));
            LDSM4(qfh[c][0], qfh[c][1], qfh[c][2], qfh[c][3], ad);
            LDSM4(qfl[c][0], qfl[c][1], qfl[c][2], qfl[c][3], ad + 8192);
        }
        __syncthreads();
    }

    // ---- zero tail of attn_w ----
    if (attw && kspan < TT) {
        float4 z = make_float4(0.f, 0.f, 0.f, 0.f);
        const int ntail4 = (TT - kspan) >> 2;
        float* wb = attw + ((size_t)(b * HH + h) * TT + q0) * TT;
        for (int i = tid; i < 64 * ntail4; i += 256) {
            int r = i / ntail4, c = i - r * ntail4;
            *(float4*)(wb + (size_t)r * TT + kspan + c * 4) = z;
        }
    }

    // ---- Pass A: l = sum exp(s), K tiles only ----
    float l0 = 0.f, l1 = 0.f;

    ISSUE_H(0, 0, CC + h * 64); CP_COMMIT();
    if (ntiles > 1) { ISSUE_H(1, STG_SZ, CC + h * 64); CP_COMMIT(); }
    for (int t = 0; t < ntiles; t++) {
        if (t + 1 < ntiles) CP_WAIT1(); else CP_WAIT0();
        __syncthreads();
        if (t + 2 < ntiles) { ISSUE_H(t + 2, ((t + 2) % 3) * STG_SZ, CC + h * 64); CP_COMMIT(); }

        float sa[4][4] = {};
        COMPUTE_S(sa, sb + (uint32_t)(t % 3) * STG_SZ);

        #pragma unroll
        for (int nt = 0; nt < 4; nt++) {
            int j0 = t * 64 + cg * 32 + nt * 8 + (lane & 3) * 2;
            l0 += __expf((j0     <= qg0) ? sa[nt][0] * scale : -1e30f);
            l0 += __expf((j0 + 1 <= qg0) ? sa[nt][1] * scale : -1e30f);
            l1 += __expf((j0     <= qg1) ? sa[nt][2] * scale : -1e30f);
            l1 += __expf((j0 + 1 <= qg1) ? sa[nt][3] * scale : -1e30f);
        }
    }
    l0 += __shfl_xor_sync(0xffffffffu, l0, 1);
    l0 += __shfl_xor_sync(0xffffffffu, l0, 2);
    l1 += __shfl_xor_sync(0xffffffffu, l1, 1);
    l1 += __shfl_xor_sync(0xffffffffu, l1, 2);
    __syncthreads();
    if ((lane & 3) == 0) { ssum[cg * 64 + lr0] = l0; ssum[cg * 64 + lr1] = l1; }
    __syncthreads();
    const float invl0 = 1.0f / (ssum[lr0] + ssum[64 + lr0]);
    const float invl1 = 1.0f / (ssum[lr1] + ssum[64 + lr1]);

    // ---- Pass B: recompute S, emit attn_w, PV (hi only) ----
    float oa[8][4] = {};
    float* wrow0 = attw ? attw + (((size_t)(b * HH + h) * TT + qg0) * TT) : (float*)0;
    float* wrow1 = attw ? attw + (((size_t)(b * HH + h) * TT + qg1) * TT) : (float*)0;

    ISSUE_H(0, 0, CC + h * 64);
    ISSUE_H(0, 8192, 2 * CC + h * 64);
    CP_COMMIT();
    if (ntiles > 1) {
        ISSUE_H(1, STG_SZ, CC + h * 64);
        ISSUE_H(1, STG_SZ + 8192, 2 * CC + h * 64);
        CP_COMMIT();
    }
    for (int t = 0; t < ntiles; t++) {
        if (t + 1 < ntiles) CP_WAIT1(); else CP_WAIT0();
        __syncthreads();
        if (t + 2 < ntiles) {
            uint32_t st = (uint32_t)((t + 2) % 3) * STG_SZ;
            ISSUE_H(t + 2, st, CC + h * 64);
            ISSUE_H(t + 2, st + 8192, 2 * CC + h * 64);
            CP_COMMIT();
        }

        const uint32_t st = (uint32_t)(t % 3) * STG_SZ;
        float sa[4][4] = {};
        COMPUTE_S(sa, sb + st);

        float p[4][4];
        #pragma unroll
        for (int nt = 0; nt < 4; nt++) {
            int j0 = t * 64 + cg * 32 + nt * 8 + (lane & 3) * 2;
            p[nt][0] = (j0     <= qg0) ? __expf(sa[nt][0] * scale) * invl0 : 0.f;
            p[nt][1] = (j0 + 1 <= qg0) ? __expf(sa[nt][1] * scale) * invl0 : 0.f;
            p[nt][2] = (j0     <= qg1) ? __expf(sa[nt][2] * scale) * invl1 : 0.f;
            p[nt][3] = (j0 + 1 <= qg1) ? __expf(sa[nt][3] * scale) * invl1 : 0.f;
            if (wrow0) {
                *(float2*)(wrow0 + j0) = make_float2(p[nt][0], p[nt][1]);
                *(float2*)(wrow1 + j0) = make_float2(p[nt][2], p[nt][3]);
            }
        }

        uint32_t pah[2][4];
        #pragma unroll
        for (int kb = 0; kb < 2; kb++) {
            pah[kb][0] = pack2h(p[2*kb][0],   p[2*kb][1]);
            pah[kb][1] = pack2h(p[2*kb][2],   p[2*kb][3]);
            pah[kb][2] = pack2h(p[2*kb+1][0], p[2*kb+1][1]);
            pah[kb][3] = pack2h(p[2*kb+1][2], p[2*kb+1][3]);
        }

        const uint32_t vbuf = sb + st + 8192;
        #pragma unroll
        for (int nd = 0; nd < 8; nd++) {
            int rv = cg * 32 + (lane >> 3) * 8 + (lane & 7);
            uint32_t ad = vbuf + (uint32_t)(rv * 128 + ((nd ^ (rv & 7)) << 4));
            uint32_t vh[4];
            LDSM4T(vh[0], vh[1], vh[2], vh[3], ad);
            #pragma unroll
            for (int kb = 0; kb < 2; kb++) {
                uint32_t bvh[2] = {vh[kb*2], vh[kb*2+1]};
                MMA16816(oa[nd], pah[kb], bvh);
            }
        }
    }
    __syncthreads();

    // ---- reduce col-group pairs, emit fp16 hi ----
    float* ored = (float*)smem;   // 64 x 64 fp32 (reuses stages)
    if (cg == 1) {
        #pragma unroll
        for (int nd = 0; nd < 8; nd++) {
            int d0 = nd * 8 + (lane & 3) * 2;
            *(float2*)&ored[lr0 * 64 + d0] = make_float2(oa[nd][0], oa[nd][1]);
            *(float2*)&ored[lr1 * 64 + d0] = make_float2(oa[nd][2], oa[nd][3]);
        }
    }
    __syncthreads();
    if (cg == 0) {
        #pragma unroll
        for (int nd = 0; nd < 8; nd++) {
            int d0 = nd * 8 + (lane & 3) * 2;
            float2 q0v = *(float2*)&ored[lr0 * 64 + d0];
            float2 q1v = *(float2*)&ored[lr1 * 64 + d0];
            size_t r1 = (size_t)(bT + qg0) * CC + h * 64 + d0;
            size_t r2 = (size_t)(bT + qg1) * CC + h * 64 + d0;
            uint32_t h0 = pack2h(oa[nd][0] + q0v.x, oa[nd][1] + q0v.y);
            uint32_t h1 = pack2h(oa[nd][2] + q1v.x, oa[nd][3] + q1v.y);
            *(uint32_t*)&oh[r1] = h0;
            *(uint32_t*)&oh[r2] = h1;
        }
    }
    #undef ISSUE_H
    #undef COMPUTE_S
}

// ---------------------------------------------------------------------------
extern "C" void kernel_launch(void* const* d_in, const int* in_sizes, int n_in,
                              void* d_out, int out_size)
{
    (void)in_sizes; (void)n_in;
    const float* x     = (const float*)d_in[0];
    const float* w_qkv = (const float*)d_in[1];
    const float* b_qkv = (const float*)d_in[2];
    const float* w_o   = (const float*)d_in[3];
    const float* b_o   = (const float*)d_in[4];
    float* out = (float*)d_out;

    __half *xhi, *xlo, *w1h, *w2h, *qh, *ql, *ahi;
    cudaGetSymbolAddress((void**)&xhi, g_xhi); cudaGetSymbolAddress((void**)&xlo, g_xlo);
    cudaGetSymbolAddress((void**)&w1h, g_w1h); cudaGetSymbolAddress((void**)&w2h, g_w2h);
    cudaGetSymbolAddress((void**)&qh, g_qh);   cudaGetSymbolAddress((void**)&ql, g_ql);
    cudaGetSymbolAddress((void**)&ahi, g_ahi);

    cudaFuncSetAttribute(mma_gemm, cudaFuncAttributeMaxDynamicSharedMemorySize, GEMM_SMEM);
    cudaFuncSetAttribute(attn_fa, cudaFuncAttributeMaxDynamicSharedMemorySize, ATTN_SMEM);

    // prep
    split_f32<<<(MM * CC + 1023) / 1024, 1024>>>(x, xhi, xlo, MM * CC);
    transpose_h<<<dim3(3 * CC / 32, CC / 32), dim3(32, 8)>>>(w_qkv, w1h, CC, 3 * CC);
    transpose_h<<<dim3(CC / 32, CC / 32), dim3(32, 8)>>>(w_o, w2h, CC, CC);

    // 1) QKV projection -> fp16 (Q cols two-pass + lo output; K/V single-pass)
    mma_gemm<<<dim3(3 * CC / 128, MM / 128), 256, GEMM_SMEM>>>(
        xhi, xlo, w1h, b_qkv, (float*)0, qh, ql, 3 * CC, CC, CC);

    // 2) attention
    size_t o_elems = (size_t)MM * CC;
    float* attw = ((size_t)out_size > o_elems) ? out + o_elems : (float*)0;
    dim3 g2(TT / 64, HH, BB);
    attn_fa<<<g2, 256, ATTN_SMEM>>>(qh, ql, attw, ahi);

    // 3) output projection (single-pass A)
    mma_gemm<<<dim3(CC / 128, MM / 128), 256, GEMM_SMEM>>>(
        ahi, ahi, w2h, b_o, out, (__half*)0, (__half*)0, CC, CC, 0);
}

// round 10
// speedup vs baseline: 8.6582x; 1.3222x over previous
#include <cuda_runtime.h>
#include <cuda_fp16.h>
#include <cstdint>

// Problem constants
#define BB 2
#define TT 2048
#define CC 1024
#define HH 16
#define DD 64
#define MM (BB*TT)   // 4096 rows

// Attention smem: 3 stages x 16KB (K hi 8KB | V hi 8KB), ssum after
#define STG_SZ   16384
#define OFF_SSUM 49152
#define ATTN_SMEM 49664

// GEMM smem: 2 stages x 32KB (Ah 16K | Bh 16K)
#define GSTG_SZ  32768
#define GEMM_SMEM (2 * GSTG_SZ)

// ---------------- scratch (no allocs allowed) ----------------
static __device__ __align__(128) __half g_xh[(size_t)MM * CC];
static __device__ __align__(128) __half g_w1h[(size_t)3 * CC * CC];
static __device__ __align__(128) __half g_w2h[(size_t)CC * CC];
static __device__ __align__(128) __half g_qkv[(size_t)MM * 3 * CC];
static __device__ __align__(128) __half g_ah[(size_t)MM * CC];

// ---------------- helpers ----------------
__device__ __forceinline__ uint32_t smem_u32(const void* p) {
    uint32_t a;
    asm("{ .reg .u64 t; cvta.to.shared.u64 t, %1; cvt.u32.u64 %0, t; }" : "=r"(a) : "l"(p));
    return a;
}

#define CPASYNC16(dst, src) \
    asm volatile("cp.async.cg.shared.global [%0], [%1], 16;" :: "r"(dst), "l"(src))
#define CP_COMMIT()  asm volatile("cp.async.commit_group;" ::: "memory")
#define CP_WAIT0()   asm volatile("cp.async.wait_group 0;" ::: "memory")
#define CP_WAIT1()   asm volatile("cp.async.wait_group 1;" ::: "memory")

#define LDSM4(r0, r1, r2, r3, addr) \
    asm volatile("ldmatrix.sync.aligned.m8n8.x4.shared.b16 {%0,%1,%2,%3}, [%4];" \
                 : "=r"(r0), "=r"(r1), "=r"(r2), "=r"(r3) : "r"(addr))

#define LDSM4T(r0, r1, r2, r3, addr) \
    asm volatile("ldmatrix.sync.aligned.m8n8.x4.trans.shared.b16 {%0,%1,%2,%3}, [%4];" \
                 : "=r"(r0), "=r"(r1), "=r"(r2), "=r"(r3) : "r"(addr))

#define MMA16816(d, a, b) \
    asm volatile("mma.sync.aligned.m16n8k16.row.col.f32.f16.f16.f32 " \
                 "{%0,%1,%2,%3}, {%4,%5,%6,%7}, {%8,%9}, {%0,%1,%2,%3};" \
                 : "+f"((d)[0]), "+f"((d)[1]), "+f"((d)[2]), "+f"((d)[3]) \
                 : "r"((a)[0]), "r"((a)[1]), "r"((a)[2]), "r"((a)[3]), \
                   "r"((b)[0]), "r"((b)[1]))

__device__ __forceinline__ uint32_t pack2h(float a, float b) {
    __half2 t;
    t.x = __float2half(a); t.y = __float2half(b);
    return *(uint32_t*)&t;
}

// ---------------------------------------------------------------------------
// prep kernels
// ---------------------------------------------------------------------------
__global__ void round_h(const float* __restrict__ in, __half* __restrict__ hi, int n) {
    int i = blockIdx.x * blockDim.x + threadIdx.x;
    if (i < n) hi[i] = __float2half(in[i]);
}

// w [K,N] f32 -> wT [N,K] fp16 (round)
__global__ void transpose_h(const float* __restrict__ w, __half* __restrict__ hi,
                            int K, int N) {
    __shared__ float t[32][33];
    int n0 = blockIdx.x * 32, k0 = blockIdx.y * 32;
    int tx = threadIdx.x, ty = threadIdx.y;
    #pragma unroll
    for (int j = 0; j < 32; j += 8)
        t[ty + j][tx] = w[(size_t)(k0 + ty + j) * N + n0 + tx];
    __syncthreads();
    #pragma unroll
    for (int j = 0; j < 32; j += 8)
        hi[(size_t)(n0 + ty + j) * K + k0 + tx] = __float2half(t[tx][ty + j]);
}

// ---------------------------------------------------------------------------
// fp16 single-pass GEMM: C[M,N] = Ah @ Bh^T + bias   (Bh as [N,K] fp16)
// 128x128 tile, BK=64, 2-stage cp.async.
// Output: fp32 C (if Chi==0) or fp16 Chi.
// ---------------------------------------------------------------------------
__global__ __launch_bounds__(256, 2) void mma_gemm(
    const __half* __restrict__ Ah, const __half* __restrict__ Bh,
    const float* __restrict__ bias,
    float* __restrict__ C, __half* __restrict__ Chi,
    int N, int K)
{
    extern __shared__ char smem[];
    const uint32_t sb = smem_u32(smem);
    const int tid = threadIdx.x;
    const int lane = tid & 31, wid = tid >> 5;
    const int warpM = wid >> 2, warpN = wid & 3;
    const int m0 = blockIdx.y * 128, n0 = blockIdx.x * 128;

    const __half* pAh = Ah + (size_t)m0 * K;
    const __half* pBh = Bh + (size_t)n0 * K;

    float acc[4][4][4] = {};
    const int nch = K >> 6;

    #define STAGE_LOAD(stg, kc) do {                                              \
        uint32_t s0_ = sb + (uint32_t)(stg) * GSTG_SZ;                            \
        _Pragma("unroll")                                                         \
        for (int i_ = 0; i_ < 4; i_++) {                                          \
            int idx_ = tid + i_ * 256;                                            \
            int row_ = idx_ >> 3, c16_ = idx_ & 7;                                \
            uint32_t so_ = (uint32_t)(row_ * 128 + ((c16_ ^ (row_ & 7)) << 4));   \
            size_t go_ = (size_t)row_ * K + (kc) + c16_ * 8;                      \
            CPASYNC16(s0_ + so_,          pAh + go_);                             \
            CPASYNC16(s0_ + 16384 + so_,  pBh + go_);                             \
        }                                                                         \
        CP_COMMIT();                                                              \
    } while (0)

    STAGE_LOAD(0, 0);

    for (int c = 0; c < nch; c++) {
        CP_WAIT0();
        __syncthreads();
        if (c + 1 < nch) STAGE_LOAD((c + 1) & 1, (c + 1) * 64);

        const uint32_t aB = sb + (uint32_t)(c & 1) * GSTG_SZ;
        const uint32_t bB = aB + 16384;

        #pragma unroll
        for (int k16 = 0; k16 < 4; k16++) {
            uint32_t ah[4][4], bh[4][2];
            #pragma unroll
            for (int mi = 0; mi < 4; mi++) {
                int row = warpM * 64 + mi * 16 + (lane & 15);
                int c16 = k16 * 2 + (lane >> 4);
                uint32_t ad = aB + (uint32_t)(row * 128 + ((c16 ^ (row & 7)) << 4));
                LDSM4(ah[mi][0], ah[mi][1], ah[mi][2], ah[mi][3], ad);
            }
            #pragma unroll
            for (int p = 0; p < 2; p++) {
                int g = lane >> 3, r = lane & 7;
                int row = warpN * 32 + p * 16 + (g >> 1) * 8 + r;
                int c16 = k16 * 2 + (g & 1);
                uint32_t bd = bB + (uint32_t)(row * 128 + ((c16 ^ (row & 7)) << 4));
                uint32_t t0, t1, t2, t3;
                LDSM4(t0, t1, t2, t3, bd);
                bh[2*p][0] = t0; bh[2*p][1] = t1; bh[2*p+1][0] = t2; bh[2*p+1][1] = t3;
            }
            #pragma unroll
            for (int mi = 0; mi < 4; mi++)
                #pragma unroll
                for (int ni = 0; ni < 4; ni++)
                    MMA16816(acc[mi][ni], ah[mi], bh[ni]);
        }
        __syncthreads();
    }

    #pragma unroll
    for (int mi = 0; mi < 4; mi++) {
        int row = m0 + warpM * 64 + mi * 16 + (lane >> 2);
        #pragma unroll
        for (int ni = 0; ni < 4; ni++) {
            int col = n0 + warpN * 32 + ni * 8 + (lane & 3) * 2;
            float b0 = bias[col], b1 = bias[col + 1];
            float v00 = acc[mi][ni][0] + b0, v01 = acc[mi][ni][1] + b1;
            float v10 = acc[mi][ni][2] + b0, v11 = acc[mi][ni][3] + b1;
            if (Chi) {
                *(uint32_t*)&Chi[(size_t)row * N + col] = pack2h(v00, v01);
                *(uint32_t*)&Chi[(size_t)(row + 8) * N + col] = pack2h(v10, v11);
            } else {
                *(float2*)&C[(size_t)row * N + col] = make_float2(v00, v01);
                *(float2*)&C[(size_t)(row + 8) * N + col] = make_float2(v10, v11);
            }
        }
    }
    #undef STAGE_LOAD
}

// ---------------------------------------------------------------------------
// Two-pass flash attention, TQ=64, single-fp16 MMA everywhere, no running max.
// ---------------------------------------------------------------------------
__global__ __launch_bounds__(256, 2) void attn_fa(
    const __half* __restrict__ qkv,
    float* __restrict__ attw, __half* __restrict__ oh)
{
    extern __shared__ char smem[];
    const uint32_t sb = smem_u32(smem);
    float* ssum = (float*)(smem + OFF_SSUM);
    const int tid = threadIdx.x, lane = tid & 31, wid = tid >> 5;
    const int rg = wid >> 1, cg = wid & 1;
    const int q0 = (int)(gridDim.x - 1 - blockIdx.x) * 64;   // big blocks first
    const int h  = blockIdx.y;
    const int b  = blockIdx.z;
    const int bT = b * TT;
    const int ntiles = (q0 >> 6) + 1;
    const int kspan  = ntiles * 64;
    const float scale = 0.125f;

    const int lr0 = rg * 16 + (lane >> 2);
    const int lr1 = lr0 + 8;
    const int qg0 = q0 + lr0, qg1 = q0 + lr1;

    #define ISSUE_H(tile, bufoff, colbase) do {                                     \
        _Pragma("unroll")                                                           \
        for (int i_ = 0; i_ < 2; i_++) {                                            \
            int idx_ = tid + i_ * 256;                                              \
            int rr_ = idx_ >> 3, cc_ = idx_ & 7;                                    \
            const __half* src_ = qkv +                                              \
                (size_t)(bT + (tile) * 64 + rr_) * 3072 + (colbase) + cc_ * 8;      \
            uint32_t dst_ = sb + (uint32_t)(bufoff) +                               \
                (uint32_t)(rr_ * 128 + ((cc_ ^ (rr_ & 7)) << 4));                   \
            CPASYNC16(dst_, src_);                                                  \
        }                                                                           \
    } while (0)

    #define COMPUTE_S(sa, kbuf) do {                                                \
        _Pragma("unroll")                                                           \
        for (int k32_ = 0; k32_ < 2; k32_++) {                                      \
            _Pragma("unroll")                                                       \
            for (int nt_ = 0; nt_ < 4; nt_++) {                                     \
                int rk_ = cg * 32 + nt_ * 8 + (lane & 7);                           \
                int c16_ = k32_ * 4 + (lane >> 3);                                  \
                uint32_t ad_ = (kbuf) + (uint32_t)(rk_ * 128 + ((c16_ ^ (rk_ & 7)) << 4)); \
                uint32_t kh_[4];                                                    \
                LDSM4(kh_[0], kh_[1], kh_[2], kh_[3], ad_);                         \
                uint32_t bh0_[2] = {kh_[0], kh_[1]}, bh1_[2] = {kh_[2], kh_[3]};    \
                MMA16816(sa[nt_], qfh[k32_*2],     bh0_);                           \
                MMA16816(sa[nt_], qfh[k32_*2 + 1], bh1_);                           \
            }                                                                       \
        }                                                                           \
    } while (0)

    // ---- Stage Q tile (hi only, 8KB) through stage 0; load fragments ----
    uint32_t qfh[4][4];
    {
        ISSUE_H(q0 >> 6, 0, h * 64);
        CP_COMMIT(); CP_WAIT0();
        __syncthreads();
        #pragma unroll
        for (int c = 0; c < 4; c++) {
            int row = rg * 16 + (lane & 15);
            int c16 = c * 2 + (lane >> 4);
            uint32_t ad = sb + (uint32_t)(row * 128 + ((c16 ^ (row & 7)) << 4));
            LDSM4(qfh[c][0], qfh[c][1], qfh[c][2], qfh[c][3], ad);
        }
        __syncthreads();
    }

    // ---- zero tail of attn_w ----
    if (attw && kspan < TT) {
        float4 z = make_float4(0.f, 0.f, 0.f, 0.f);
        const int ntail4 = (TT - kspan) >> 2;
        float* wb = attw + ((size_t)(b * HH + h) * TT + q0) * TT;
        for (int i = tid; i < 64 * ntail4; i += 256) {
            int r = i / ntail4, c = i - r * ntail4;
            *(float4*)(wb + (size_t)r * TT + kspan + c * 4) = z;
        }
    }

    // ---- Pass A: l = sum exp(s), K tiles only ----
    float l0 = 0.f, l1 = 0.f;

    ISSUE_H(0, 0, CC + h * 64); CP_COMMIT();
    if (ntiles > 1) { ISSUE_H(1, STG_SZ, CC + h * 64); CP_COMMIT(); }
    for (int t = 0; t < ntiles; t++) {
        if (t + 1 < ntiles) CP_WAIT1(); else CP_WAIT0();
        __syncthreads();
        if (t + 2 < ntiles) { ISSUE_H(t + 2, ((t + 2) % 3) * STG_SZ, CC + h * 64); CP_COMMIT(); }

        float sa[4][4] = {};
        COMPUTE_S(sa, sb + (uint32_t)(t % 3) * STG_SZ);

        #pragma unroll
        for (int nt = 0; nt < 4; nt++) {
            int j0 = t * 64 + cg * 32 + nt * 8 + (lane & 3) * 2;
            l0 += __expf((j0     <= qg0) ? sa[nt][0] * scale : -1e30f);
            l0 += __expf((j0 + 1 <= qg0) ? sa[nt][1] * scale : -1e30f);
            l1 += __expf((j0     <= qg1) ? sa[nt][2] * scale : -1e30f);
            l1 += __expf((j0 + 1 <= qg1) ? sa[nt][3] * scale : -1e30f);
        }
    }
    l0 += __shfl_xor_sync(0xffffffffu, l0, 1);
    l0 += __shfl_xor_sync(0xffffffffu, l0, 2);
    l1 += __shfl_xor_sync(0xffffffffu, l1, 1);
    l1 += __shfl_xor_sync(0xffffffffu, l1, 2);
    __syncthreads();
    if ((lane & 3) == 0) { ssum[cg * 64 + lr0] = l0; ssum[cg * 64 + lr1] = l1; }
    __syncthreads();
    const float invl0 = 1.0f / (ssum[lr0] + ssum[64 + lr0]);
    const float invl1 = 1.0f / (ssum[lr1] + ssum[64 + lr1]);

    // ---- Pass B: recompute S, emit attn_w, PV ----
    float oa[8][4] = {};
    float* wrow0 = attw ? attw + (((size_t)(b * HH + h) * TT + qg0) * TT) : (float*)0;
    float* wrow1 = attw ? attw + (((size_t)(b * HH + h) * TT + qg1) * TT) : (float*)0;

    ISSUE_H(0, 0, CC + h * 64);
    ISSUE_H(0, 8192, 2 * CC + h * 64);
    CP_COMMIT();
    if (ntiles > 1) {
        ISSUE_H(1, STG_SZ, CC + h * 64);
        ISSUE_H(1, STG_SZ + 8192, 2 * CC + h * 64);
        CP_COMMIT();
    }
    for (int t = 0; t < ntiles; t++) {
        if (t + 1 < ntiles) CP_WAIT1(); else CP_WAIT0();
        __syncthreads();
        if (t + 2 < ntiles) {
            uint32_t st = (uint32_t)((t + 2) % 3) * STG_SZ;
            ISSUE_H(t + 2, st, CC + h * 64);
            ISSUE_H(t + 2, st + 8192, 2 * CC + h * 64);
            CP_COMMIT();
        }

        const uint32_t st = (uint32_t)(t % 3) * STG_SZ;
        float sa[4][4] = {};
        COMPUTE_S(sa, sb + st);

        float p[4][4];
        #pragma unroll
        for (int nt = 0; nt < 4; nt++) {
            int j0 = t * 64 + cg * 32 + nt * 8 + (lane & 3) * 2;
            p[nt][0] = (j0     <= qg0) ? __expf(sa[nt][0] * scale) * invl0 : 0.f;
            p[nt][1] = (j0 + 1 <= qg0) ? __expf(sa[nt][1] * scale) * invl0 : 0.f;
            p[nt][2] = (j0     <= qg1) ? __expf(sa[nt][2] * scale) * invl1 : 0.f;
            p[nt][3] = (j0 + 1 <= qg1) ? __expf(sa[nt][3] * scale) * invl1 : 0.f;
            if (wrow0) {
                *(float2*)(wrow0 + j0) = make_float2(p[nt][0], p[nt][1]);
                *(float2*)(wrow1 + j0) = make_float2(p[nt][2], p[nt][3]);
            }
        }

        uint32_t pah[2][4];
        #pragma unroll
        for (int kb = 0; kb < 2; kb++) {
            pah[kb][0] = pack2h(p[2*kb][0],   p[2*kb][1]);
            pah[kb][1] = pack2h(p[2*kb][2],   p[2*kb][3]);
            pah[kb][2] = pack2h(p[2*kb+1][0], p[2*kb+1][1]);
            pah[kb][3] = pack2h(p[2*kb+1][2], p[2*kb+1][3]);
        }

        const uint32_t vbuf = sb + st + 8192;
        #pragma unroll
        for (int nd = 0; nd < 8; nd++) {
            int rv = cg * 32 + (lane >> 3) * 8 + (lane & 7);
            uint32_t ad = vbuf + (uint32_t)(rv * 128 + ((nd ^ (rv & 7)) << 4));
            uint32_t vh[4];
            LDSM4T(vh[0], vh[1], vh[2], vh[3], ad);
            #pragma unroll
            for (int kb = 0; kb < 2; kb++) {
                uint32_t bvh[2] = {vh[kb*2], vh[kb*2+1]};
                MMA16816(oa[nd], pah[kb], bvh);
            }
        }
    }
    __syncthreads();

    // ---- reduce col-group pairs, emit fp16 ----
    float* ored = (float*)smem;   // 64 x 64 fp32 (reuses stages)
    if (cg == 1) {
        #pragma unroll
        for (int nd = 0; nd < 8; nd++) {
            int d0 = nd * 8 + (lane & 3) * 2;
            *(float2*)&ored[lr0 * 64 + d0] = make_float2(oa[nd][0], oa[nd][1]);
            *(float2*)&ored[lr1 * 64 + d0] = make_float2(oa[nd][2], oa[nd][3]);
        }
    }
    __syncthreads();
    if (cg == 0) {
        #pragma unroll
        for (int nd = 0; nd < 8; nd++) {
            int d0 = nd * 8 + (lane & 3) * 2;
            float2 q0v = *(float2*)&ored[lr0 * 64 + d0];
            float2 q1v = *(float2*)&ored[lr1 * 64 + d0];
            size_t r1 = (size_t)(bT + qg0) * CC + h * 64 + d0;
            size_t r2 = (size_t)(bT + qg1) * CC + h * 64 + d0;
            *(uint32_t*)&oh[r1] = pack2h(oa[nd][0] + q0v.x, oa[nd][1] + q0v.y);
            *(uint32_t*)&oh[r2] = pack2h(oa[nd][2] + q1v.x, oa[nd][3] + q1v.y);
        }
    }
    #undef ISSUE_H
    #undef COMPUTE_S
}

// ---------------------------------------------------------------------------
extern "C" void kernel_launch(void* const* d_in, const int* in_sizes, int n_in,
                              void* d_out, int out_size)
{
    (void)in_sizes; (void)n_in;
    const float* x     = (const float*)d_in[0];
    const float* w_qkv = (const float*)d_in[1];
    const float* b_qkv = (const float*)d_in[2];
    const float* w_o   = (const float*)d_in[3];
    const float* b_o   = (const float*)d_in[4];
    float* out = (float*)d_out;

    __half *xh, *w1h, *w2h, *qkv, *ah;
    cudaGetSymbolAddress((void**)&xh, g_xh);
    cudaGetSymbolAddress((void**)&w1h, g_w1h); cudaGetSymbolAddress((void**)&w2h, g_w2h);
    cudaGetSymbolAddress((void**)&qkv, g_qkv); cudaGetSymbolAddress((void**)&ah, g_ah);

    cudaFuncSetAttribute(mma_gemm, cudaFuncAttributeMaxDynamicSharedMemorySize, GEMM_SMEM);
    cudaFuncSetAttribute(attn_fa, cudaFuncAttributeMaxDynamicSharedMemorySize, ATTN_SMEM);

    // prep
    round_h<<<(MM * CC + 1023) / 1024, 1024>>>(x, xh, MM * CC);
    transpose_h<<<dim3(3 * CC / 32, CC / 32), dim3(32, 8)>>>(w_qkv, w1h, CC, 3 * CC);
    transpose_h<<<dim3(CC / 32, CC / 32), dim3(32, 8)>>>(w_o, w2h, CC, CC);

    // 1) QKV projection -> fp16 (single-pass)
    mma_gemm<<<dim3(3 * CC / 128, MM / 128), 256, GEMM_SMEM>>>(
        xh, w1h, b_qkv, (float*)0, qkv, 3 * CC, CC);

    // 2) attention (two-pass flash, single-fp16)
    size_t o_elems = (size_t)MM * CC;
    float* attw = ((size_t)out_size > o_elems) ? out + o_elems : (float*)0;
    dim3 g2(TT / 64, HH, BB);
    attn_fa<<<g2, 256, ATTN_SMEM>>>(qkv, attw, ah);

    // 3) output projection (fp32 out)
    mma_gemm<<<dim3(CC / 128, MM / 128), 256, GEMM_SMEM>>>(
        ah, w2h, b_o, out, (__half*)0, CC, CC);
}